// round 8
// baseline (speedup 1.0000x reference)
#include <cuda_runtime.h>
#include <math.h>

#define D_MODEL 256
#define N_STATE 64
#define LSEQ    2048
#define L2X     4096
#define NBATCH  16

typedef unsigned long long ull;

// Scratch (no cudaMalloc allowed).
__device__ float2 g_at[D_MODEL * LSEQ];   // 4 MB
__device__ float2 g_kf[D_MODEL * L2X];    // 8 MB, NATURAL frequency order

static __device__ __forceinline__ float2 cmul(float2 a, float2 b) {
    return make_float2(a.x * b.x - a.y * b.y, a.x * b.y + a.y * b.x);
}
static __device__ __forceinline__ float2 cadd(float2 a, float2 b) {
    return make_float2(a.x + b.x, a.y + b.y);
}
static __device__ __forceinline__ float2 csub(float2 a, float2 b) {
    return make_float2(a.x - b.x, a.y - b.y);
}

static __device__ __forceinline__ void barsync(int id, int nthr) {
    asm volatile("bar.sync %0, %1;" :: "r"(id), "r"(nthr) : "memory");
}

// packed f32x2 ops (sm_103a; FFMA2 only reachable via PTX)
#define F2ADD(d,a,b)   asm("add.rn.f32x2 %0,%1,%2;"    : "=l"(d) : "l"(a), "l"(b))
#define F2MUL(d,a,b)   asm("mul.rn.f32x2 %0,%1,%2;"    : "=l"(d) : "l"(a), "l"(b))
#define F2FMA(d,a,b,c) asm("fma.rn.f32x2 %0,%1,%2,%3;" : "=l"(d) : "l"(a), "l"(b), "l"(c))
#define F2PACK(d,lo,hi) asm("mov.b64 %0,{%1,%2};" : "=l"(d) : "f"(lo), "f"(hi))
#define F2UNPK(lo,hi,v) asm("mov.b64 {%0,%1},%2;" : "=f"(lo), "=f"(hi) : "l"(v))
#define FRCP(d,a)      asm("rcp.approx.f32 %0,%1;" : "=f"(d) : "f"(a))

// Triple-pad smem addressing: conflict-free for strides 256, 16, 1.
#define PIDX(a) ((a) + ((a) >> 4) + ((a) >> 8))

// radix-16 digit reversal for N=4096 (digits 16,16,16)
static __device__ __forceinline__ int rev16(int k) {
    return ((k & 15) << 8) | (k & 240) | (k >> 8);
}

// output slot permutation of bfly16: X[q] lives in v[PERM16(q)]
#define PERM16(q) ((((q) & 3) << 2) | ((q) >> 2))

// ---------------------------------------------------------------------------
// DFT4 (INV=false: W4=-i forward; INV=true: +i)
// ---------------------------------------------------------------------------
template<bool INV>
static __device__ __forceinline__ void dft4(float2& a, float2& b, float2& c, float2& d)
{
    float2 t0 = cadd(a, c), t1 = csub(a, c), t2 = cadd(b, d), t3 = csub(b, d);
    float2 j3 = INV ? make_float2(-t3.y, t3.x) : make_float2(t3.y, -t3.x);
    a = cadd(t0, t2); c = csub(t0, t2);
    b = cadd(t1, j3); d = csub(t1, j3);
}

template<bool INV>
static __device__ __forceinline__ float2 cmulw(float2 x, float wr, float wi)
{
    return cmul(x, make_float2(wr, INV ? -wi : wi));
}

// ---------------------------------------------------------------------------
// 16-point DFT in registers. Input natural v[n]; output X[q] at v[PERM16(q)].
// ---------------------------------------------------------------------------
template<bool INV>
static __device__ __forceinline__ void bfly16(float2 v[16])
{
    const float C1 = 0.9238795325112867f, S1 = 0.3826834323650898f, R2 = 0.7071067811865476f;
    dft4<INV>(v[0], v[4], v[8],  v[12]);
    dft4<INV>(v[1], v[5], v[9],  v[13]);
    dft4<INV>(v[2], v[6], v[10], v[14]);
    dft4<INV>(v[3], v[7], v[11], v[15]);
    v[5]  = cmulw<INV>(v[5],  C1, -S1);   // W^1
    v[6]  = cmulw<INV>(v[6],  R2, -R2);   // W^2
    v[7]  = cmulw<INV>(v[7],  S1, -C1);   // W^3
    v[9]  = cmulw<INV>(v[9],  R2, -R2);   // W^2
    v[10] = cmulw<INV>(v[10], 0.f, -1.f); // W^4
    v[11] = cmulw<INV>(v[11], -R2, -R2);  // W^6
    v[13] = cmulw<INV>(v[13], S1, -C1);   // W^3
    v[14] = cmulw<INV>(v[14], -R2, -R2);  // W^6
    v[15] = cmulw<INV>(v[15], -C1,  S1);  // W^9
    dft4<INV>(v[0],  v[1],  v[2],  v[3]);
    dft4<INV>(v[4],  v[5],  v[6],  v[7]);
    dft4<INV>(v[8],  v[9],  v[10], v[11]);
    dft4<INV>(v[12], v[13], v[14], v[15]);
}

// multiply by powers of w1: FREQ=true -> v[q] *= w1^q ; else v[PERM16(q)] *= w1^q
template<bool FREQ>
static __device__ __forceinline__ void twapply16(float2 v[16], float2 w1)
{
#define TSLOT(q) (FREQ ? (q) : PERM16(q))
    float2 w2 = cmul(w1, w1);
    v[TSLOT(1)] = cmul(v[TSLOT(1)], w1);
    v[TSLOT(2)] = cmul(v[TSLOT(2)], w2);
    float2 w3 = cmul(w2, w1);
    v[TSLOT(3)] = cmul(v[TSLOT(3)], w3);
    float2 w4 = cmul(w2, w2);
    v[TSLOT(4)] = cmul(v[TSLOT(4)], w4);
    float2 w5 = cmul(w4, w1);
    v[TSLOT(5)] = cmul(v[TSLOT(5)], w5);
    float2 w6 = cmul(w4, w2);
    v[TSLOT(6)] = cmul(v[TSLOT(6)], w6);
    float2 w7 = cmul(w4, w3);
    v[TSLOT(7)] = cmul(v[TSLOT(7)], w7);
    float2 w8 = cmul(w4, w4);
    v[TSLOT(8)]  = cmul(v[TSLOT(8)],  w8);
    v[TSLOT(9)]  = cmul(v[TSLOT(9)],  cmul(w8, w1));
    v[TSLOT(10)] = cmul(v[TSLOT(10)], cmul(w8, w2));
    v[TSLOT(11)] = cmul(v[TSLOT(11)], cmul(w8, w3));
    v[TSLOT(12)] = cmul(v[TSLOT(12)], cmul(w8, w4));
    v[TSLOT(13)] = cmul(v[TSLOT(13)], cmul(w8, w5));
    v[TSLOT(14)] = cmul(v[TSLOT(14)], cmul(w8, w6));
    v[TSLOT(15)] = cmul(v[TSLOT(15)], cmul(w8, w7));
#undef TSLOT
}

// ---------------------------------------------------------------------------
// In-place radix-16 stage. Forward DIF; inverse DIT. tw[k] = W_4096^k.
// ---------------------------------------------------------------------------
template<bool INV>
static __device__ void stage16(float2* buf, const float2* __restrict__ tw,
                               int L, int NB, int gtid, int GT)
{
    const int m = L >> 4;
    const int twstep = L2X / L;
    for (int b = gtid; b < NB; b += GT) {
        int j = b & (m - 1);
        int base = ((b - j) << 4) + j;
        float2 v[16];
        #pragma unroll
        for (int r = 0; r < 16; r++) v[r] = buf[PIDX(base + m * r)];

        if (!INV) {
            bfly16<false>(v);
            if (m > 1) {
                float2 w1 = tw[j * twstep];
                twapply16<false>(v, w1);
            }
        } else {
            if (m > 1) {
                float2 w1 = tw[j * twstep]; w1.y = -w1.y;
                twapply16<true>(v, w1);
            }
            bfly16<true>(v);
        }
        #pragma unroll
        for (int q = 0; q < 16; q++) buf[PIDX(base + m * q)] = v[PERM16(q)];
    }
}

// ---------------------------------------------------------------------------
// 8-point DFT + radix-8 DIF stage (kf's 2048 = 8*16*16 first stage)
// ---------------------------------------------------------------------------
template<bool INV>
static __device__ __forceinline__ void bfly8(float2 v[8])
{
    const float t = 0.70710678118654752f;
    float2 a0 = cadd(v[0], v[4]), a4 = csub(v[0], v[4]);
    float2 a1 = cadd(v[1], v[5]), a5 = csub(v[1], v[5]);
    float2 a2 = cadd(v[2], v[6]), a6 = csub(v[2], v[6]);
    float2 a3 = cadd(v[3], v[7]), a7 = csub(v[3], v[7]);
    float2 b0 = cadd(a0, a2), b2 = csub(a0, a2);
    float2 b1 = cadd(a1, a3), b3 = csub(a1, a3);
    float2 m4b3 = INV ? make_float2(-b3.y, b3.x) : make_float2(b3.y, -b3.x);
    v[0] = cadd(b0, b1);  v[4] = csub(b0, b1);
    v[2] = cadd(b2, m4b3); v[6] = csub(b2, m4b3);
    float2 c0 = a4;
    float2 c1 = INV ? make_float2(t * (a5.x - a5.y), t * (a5.x + a5.y))
                    : make_float2(t * (a5.x + a5.y), t * (a5.y - a5.x));
    float2 c2 = INV ? make_float2(-a6.y, a6.x) : make_float2(a6.y, -a6.x);
    float2 c3 = INV ? make_float2(-t * (a7.x + a7.y), t * (a7.x - a7.y))
                    : make_float2(t * (a7.y - a7.x), -t * (a7.x + a7.y));
    float2 d0 = cadd(c0, c2), d2 = csub(c0, c2);
    float2 d1 = cadd(c1, c3), d3 = csub(c1, c3);
    float2 m4d3 = INV ? make_float2(-d3.y, d3.x) : make_float2(d3.y, -d3.x);
    v[1] = cadd(d0, d1);  v[5] = csub(d0, d1);
    v[3] = cadd(d2, m4d3); v[7] = csub(d2, m4d3);
}

template<bool INV>
static __device__ void stage8(float2* buf, const float2* __restrict__ tw,
                              int L, int NB, int gtid, int GT)
{
    int m = L >> 3;
    int twstep = L2X / L;
    for (int b = gtid; b < NB; b += GT) {
        int j = b & (m - 1);
        int base = ((b - j) << 3) + j;
        float2 v[8];
        #pragma unroll
        for (int r = 0; r < 8; r++) v[r] = buf[PIDX(base + m * r)];

        if (m > 1) {
            float2 w = tw[j * twstep];
            if (INV) w.y = -w.y;
            if (!INV) {
                bfly8<false>(v);
                float2 wq = w;
                v[1] = cmul(v[1], wq);
                #pragma unroll
                for (int q = 2; q < 8; q++) { wq = cmul(wq, w); v[q] = cmul(v[q], wq); }
            } else {
                float2 wq = w;
                v[1] = cmul(v[1], wq);
                #pragma unroll
                for (int q = 2; q < 8; q++) { wq = cmul(wq, w); v[q] = cmul(v[q], wq); }
                bfly8<true>(v);
            }
        } else {
            bfly8<INV>(v);
        }
        #pragma unroll
        for (int r = 0; r < 8; r++) buf[PIDX(base + m * r)] = v[r];
    }
}

// ---------------------------------------------------------------------------
// Stage A: at_roots via Woodbury. 4 j per thread = two independent f32x2
// chains per thread (ILP for the RCP->mul->FMA latency chain); coefficient
// LDS shared across both chains. grid (256, 2).
// omega trig MUST be precise sincosf (MUFU sin==0 at pi -> NaN).
// ---------------------------------------------------------------------------
__global__ __launch_bounds__(256)
void at_roots_kernel(const float* __restrict__ p_ri,
                     const float* __restrict__ lambda_ri,
                     const float* __restrict__ B_ri,
                     const float* __restrict__ Ct_ri,
                     const float* __restrict__ log_step)
{
    __shared__ ull s_nlx[N_STATE], s_nly[N_STATE];
    __shared__ ull s_cbx[N_STATE], s_cby[N_STATE];
    __shared__ ull s_cpx[N_STATE], s_cpy[N_STATE];
    __shared__ ull s_pbx[N_STATE], s_pby[N_STATE];
    __shared__ ull s_pp [N_STATE];

    int d = blockIdx.x;
    int jlo = blockIdx.y * 1024;
    int tid = threadIdx.x;

    if (tid < N_STATE) {
        int n = tid;
        float pr = p_ri[2 * n], pi = p_ri[2 * n + 1];
        float2 lam = make_float2(lambda_ri[2 * n], lambda_ri[2 * n + 1]);
        float2 Bv  = make_float2(B_ri[(d * N_STATE + n) * 2], B_ri[(d * N_STATE + n) * 2 + 1]);
        float2 Ctc = make_float2(Ct_ri[(d * N_STATE + n) * 2], -Ct_ri[(d * N_STATE + n) * 2 + 1]);
        float2 CtB = cmul(Ctc, Bv);
        float2 Ctp = cmul(Ctc, make_float2(pr, pi));
        float2 pB  = cmul(make_float2(pr, -pi), Bv);
        float  pp  = pr * pr + pi * pi;
        F2PACK(s_nlx[n], -lam.x, -lam.x);
        F2PACK(s_nly[n], -lam.y, -lam.y);
        F2PACK(s_cbx[n], CtB.x, CtB.x);  F2PACK(s_cby[n], CtB.y, CtB.y);
        F2PACK(s_cpx[n], Ctp.x, Ctp.x);  F2PACK(s_cpy[n], Ctp.y, Ctp.y);
        F2PACK(s_pbx[n], pB.x,  pB.x);   F2PACK(s_pby[n], pB.y,  pB.y);
        F2PACK(s_pp [n], pp,    pp);
    }
    __syncthreads();

    float tos = 2.0f * __expf(-log_step[d]);

    int j0 = jlo + 4 * tid;

    float gx[4], gy[4], ccx[4], ccy[4];
    #pragma unroll
    for (int e = 0; e < 4; e++) {
        int j = j0 + e;
        float ang = 6.283185307179586f * (float)j * (1.0f / (float)LSEQ);
        float sj, cj;
        sincosf(ang, &sj, &cj);
        float2 onep = make_float2(1.0f + cj, sj);
        float2 onem = make_float2(1.0f - cj, -sj);
        float mag = fmaxf(onep.x * onep.x + onep.y * onep.y, 1e-30f);
        float rp = 1.0f / mag;
        float2 ip = make_float2(onep.x * rp, -onep.y * rp);
        ccx[e] = 2.0f * ip.x; ccy[e] = 2.0f * ip.y;
        float2 gq = cmul(onem, ip);
        gx[e] = tos * gq.x; gy[e] = tos * gq.y;
    }
    ull gx2[2], gy2[2];
    F2PACK(gx2[0], gx[0], gx[1]); F2PACK(gy2[0], gy[0], gy[1]);
    F2PACK(gx2[1], gx[2], gx[3]); F2PACK(gy2[1], gy[2], gy[3]);

    ull k00x[2] = {0,0}, k00y[2] = {0,0}, k00s[2] = {0,0};
    ull k01x[2] = {0,0}, k01y[2] = {0,0}, k01s[2] = {0,0};
    ull k10x[2] = {0,0}, k10y[2] = {0,0}, k10s[2] = {0,0};
    ull k11x[2] = {0,0}, k11s[2] = {0,0};

    #pragma unroll 4
    for (int n = 0; n < N_STATE; n++) {
        ull cbx = s_cbx[n], cby = s_cby[n];
        ull cpx = s_cpx[n], cpy = s_cpy[n];
        ull pbx = s_pbx[n], pby = s_pby[n];
        ull ppv = s_pp[n];
        ull nlx = s_nlx[n], nly = s_nly[n];
        #pragma unroll
        for (int h = 0; h < 2; h++) {
            ull dcx, dcy, m2, r, ix, t, tmp;
            F2ADD(dcx, gx2[h], nlx);
            F2ADD(dcy, gy2[h], nly);
            F2MUL(tmp, dcx, dcx);
            F2FMA(m2, dcy, dcy, tmp);
            float mlo, mhi, rlo, rhi;
            F2UNPK(mlo, mhi, m2);
            FRCP(rlo, mlo);
            FRCP(rhi, mhi);
            F2PACK(r, rlo, rhi);
            F2MUL(ix, dcx, r);
            F2MUL(t,  dcy, r);
            F2FMA(k00x[h], cbx, ix, k00x[h]);
            F2FMA(k00x[h], cby, t,  k00x[h]);
            F2FMA(k00y[h], cby, ix, k00y[h]);
            F2FMA(k00s[h], cbx, t,  k00s[h]);
            F2FMA(k01x[h], cpx, ix, k01x[h]);
            F2FMA(k01x[h], cpy, t,  k01x[h]);
            F2FMA(k01y[h], cpy, ix, k01y[h]);
            F2FMA(k01s[h], cpx, t,  k01s[h]);
            F2FMA(k10x[h], pbx, ix, k10x[h]);
            F2FMA(k10x[h], pby, t,  k10x[h]);
            F2FMA(k10y[h], pby, ix, k10y[h]);
            F2FMA(k10s[h], pbx, t,  k10s[h]);
            F2FMA(k11x[h], ppv, ix, k11x[h]);
            F2FMA(k11s[h], ppv, t,  k11s[h]);
        }
    }

    float a00x[4], a00y[4], a01x[4], a01y[4], a10x[4], a10y[4], a11x[4], a11y[4];
    #pragma unroll
    for (int h = 0; h < 2; h++) {
        F2UNPK(a00x[2*h], a00x[2*h+1], k00x[h]);
        { float y0,y1,s0,s1; F2UNPK(y0,y1,k00y[h]); F2UNPK(s0,s1,k00s[h]); a00y[2*h]=y0-s0; a00y[2*h+1]=y1-s1; }
        F2UNPK(a01x[2*h], a01x[2*h+1], k01x[h]);
        { float y0,y1,s0,s1; F2UNPK(y0,y1,k01y[h]); F2UNPK(s0,s1,k01s[h]); a01y[2*h]=y0-s0; a01y[2*h+1]=y1-s1; }
        F2UNPK(a10x[2*h], a10x[2*h+1], k10x[h]);
        { float y0,y1,s0,s1; F2UNPK(y0,y1,k10y[h]); F2UNPK(s0,s1,k10s[h]); a10y[2*h]=y0-s0; a10y[2*h+1]=y1-s1; }
        F2UNPK(a11x[2*h], a11x[2*h+1], k11x[h]);
        { float s0,s1; F2UNPK(s0,s1,k11s[h]); a11y[2*h]=-s0; a11y[2*h+1]=-s1; }
    }

    float4 outv[2];
    #pragma unroll
    for (int e = 0; e < 4; e++) {
        float2 k00 = make_float2(a00x[e], a00y[e]);
        float2 k01 = make_float2(a01x[e], a01y[e]);
        float2 k10 = make_float2(a10x[e], a10y[e]);
        float2 den = make_float2(1.0f + a11x[e], a11y[e]);
        float rd = __fdividef(1.0f, den.x * den.x + den.y * den.y);
        float2 iden = make_float2(den.x * rd, -den.y * rd);
        float2 frac = cmul(cmul(k01, k10), iden);
        float2 res  = cmul(make_float2(ccx[e], ccy[e]), csub(k00, frac));
        if (e & 1) { outv[e >> 1].z = res.x; outv[e >> 1].w = res.y; }
        else       { outv[e >> 1].x = res.x; outv[e >> 1].y = res.y; }
    }
    *(float4*)&g_at[d * LSEQ + j0]     = outv[0];
    *(float4*)&g_at[d * LSEQ + j0 + 2] = outv[1];
}

// ---------------------------------------------------------------------------
// Stage B: per channel d:
//   K = Re(DFT_2048(at_roots))/2048 ; Kf = DFT_4096(pad(K)) natural order.
// 2048 = 8*16*16; 4096 = 16^3.
// ---------------------------------------------------------------------------
__global__ void kf_kernel()
{
    extern __shared__ float2 sm[];
    float2* tw   = sm;                 // 512 (W_4096^k, k<512)
    float2* bufA = sm + 512;           // padded 2048 -> 2184
    float2* bufB = sm + 512 + 2184;    // padded 4096 -> 4368

    int d = blockIdx.x;
    int tid = threadIdx.x;
    const int T = 256;

    for (int k = tid; k < 512; k += T) {
        float s, c;
        sincosf(6.283185307179586f * (float)k * (1.0f / 4096.0f), &s, &c);
        tw[k] = make_float2(c, -s);
    }
    for (int j = tid; j < LSEQ; j += T) bufA[PIDX(j)] = g_at[d * LSEQ + j];
    __syncthreads();

    // ---- FFT-2048 forward: radices 8,16,16 ----
    stage8 <false>(bufA, tw, 2048, 256, tid, T); __syncthreads();
    stage16<false>(bufA, tw,  256, 128, tid, T); __syncthreads();
    stage16<false>(bufA, tw,   16, 128, tid, T); __syncthreads();

    // ---- pad K (un-digit-reverse: l = l0 + 8 l1 + 128 l2 -> p = 256 l0 + 16 l1 + l2)
    for (int l = tid; l < LSEQ; l += T) {
        int p = ((l & 7) << 8) | (((l >> 3) & 15) << 4) | ((l >> 7) & 15);
        bufB[PIDX(l)] = make_float2(bufA[PIDX(p)].x * (1.0f / (float)LSEQ), 0.0f);
        bufB[PIDX(l + LSEQ)] = make_float2(0.0f, 0.0f);
    }
    __syncthreads();

    // ---- FFT-4096 forward: 16^3 ----
    stage16<false>(bufB, tw, 4096, 256, tid, T); __syncthreads();
    stage16<false>(bufB, tw,  256, 256, tid, T); __syncthreads();
    stage16<false>(bufB, tw,   16, 256, tid, T); __syncthreads();

    // natural-order coalesced global write
    for (int k = tid; k < L2X; k += T)
        g_kf[d * L2X + k] = bufB[PIDX(rev16(k))];
}

// ---------------------------------------------------------------------------
// Stage C: causal FFT conv. 4 channels/block, 2 groups x 128 threads.
// First fwd stage fused with gmem load (zero-padded half folds away);
// last inv stage fused with gmem store (only l<2048 written).
// Middle: radix-16 smem stages; pointwise in digit-reversed order.
// ---------------------------------------------------------------------------
__global__ __launch_bounds__(256, 3)
void conv_kernel(const float* __restrict__ u,
                 const float* __restrict__ Dp,
                 float* __restrict__ y)
{
    extern __shared__ float2 sm[];
    float2* tw = sm;                          // 256 (W_4096^k, k<256)

    int tid = threadIdx.x;
    int q   = tid >> 7;                       // group 0..1
    int gt  = tid & 127;
    float2* buf = sm + 256 + q * 4368;        // padded 4096 per group

    int b  = blockIdx.x >> 6;                 // 16 batches
    int c0 = (blockIdx.x & 63) * 4 + 2 * q;   // channel pair
    int barId = 1 + q;

    if (tid < 256) {
        float s, c;
        sincosf(6.283185307179586f * (float)tid * (1.0f / 4096.0f), &s, &c);
        tw[tid] = make_float2(c, -s);
    }
    __syncthreads();

    const float* ub = u + (size_t)b * LSEQ * D_MODEL + c0;

    // ---- fused: load z = u[:,c0]+i*u[:,c0+1] (pad 2048 zeros) + first fwd
    // stage (L=4096, m=256). Butterfly j reads l = j + 256r, r<8 nonzero.
    for (int j = gt; j < 256; j += 128) {
        float2 v[16];
        #pragma unroll
        for (int r = 0; r < 8; r++)
            v[r] = *(const float2*)&ub[(size_t)(j + 256 * r) * D_MODEL];
        #pragma unroll
        for (int r = 8; r < 16; r++) v[r] = make_float2(0.0f, 0.0f);
        bfly16<false>(v);
        twapply16<false>(v, tw[j]);
        #pragma unroll
        for (int p = 0; p < 16; p++) buf[PIDX(j + 256 * p)] = v[PERM16(p)];
    }
    barsync(barId, 128);

    stage16<false>(buf, tw,  256, 256, gt, 128); barsync(barId, 128);
    stage16<false>(buf, tw,   16, 256, gt, 128); barsync(barId, 128);

    // unpack packed real spectra, multiply by Kf, repack (digit-reversed smem)
    for (int k = gt; k <= 2048; k += 128) {
        int mk = (L2X - k) & (L2X - 1);
        int pk = PIDX(rev16(k));
        int pm = PIDX(rev16(mk));
        float2 Zk = buf[pk], Zm = buf[pm];
        float2 U0 = make_float2(0.5f * (Zk.x + Zm.x), 0.5f * (Zk.y - Zm.y));
        float2 U1 = make_float2(0.5f * (Zk.y + Zm.y), 0.5f * (Zm.x - Zk.x));
        float2 H0 = g_kf[(size_t)c0 * L2X + k];
        float2 H1 = g_kf[(size_t)(c0 + 1) * L2X + k];
        float2 Y0 = cmul(U0, H0);
        float2 Y1 = cmul(U1, H1);
        buf[pk] = make_float2(Y0.x - Y1.y, Y0.y + Y1.x);          // Y0 + i*Y1
        if (k != 0 && k != 2048)
            buf[pm] = make_float2(Y0.x + Y1.y, Y1.x - Y0.y);      // conj(Y0)+i*conj(Y1)
    }
    barsync(barId, 128);

    stage16<true>(buf, tw,   16, 256, gt, 128); barsync(barId, 128);
    stage16<true>(buf, tw,  256, 256, gt, 128); barsync(barId, 128);

    // ---- fused: last inv stage (L=4096, m=256) + store. Natural output
    // position of slot q is l = j + 256q; only q<8 lands in l<2048.
    float d0 = Dp[c0], d1 = Dp[c0 + 1];
    const float invN = 1.0f / (float)L2X;
    float* yb = y + (size_t)b * LSEQ * D_MODEL + c0;
    for (int j = gt; j < 256; j += 128) {
        float2 v[16];
        #pragma unroll
        for (int r = 0; r < 16; r++) v[r] = buf[PIDX(j + 256 * r)];
        float2 w1 = tw[j]; w1.y = -w1.y;
        twapply16<true>(v, w1);
        bfly16<true>(v);
        #pragma unroll
        for (int p = 0; p < 8; p++) {
            size_t idx = (size_t)(j + 256 * p) * D_MODEL;
            float2 uv = *(const float2*)&ub[idx];
            float2 res = v[PERM16(p)];
            float2 o = make_float2(res.x * invN + d0 * uv.x,
                                   res.y * invN + d1 * uv.y);
            *(float2*)&yb[idx] = o;
        }
    }
}

// ---------------------------------------------------------------------------
extern "C" void kernel_launch(void* const* d_in, const int* in_sizes, int n_in,
                              void* d_out, int out_size)
{
    const float* u         = (const float*)d_in[0];
    const float* p_ri      = (const float*)d_in[1];
    const float* lambda_ri = (const float*)d_in[2];
    const float* B_ri      = (const float*)d_in[3];
    const float* Ct_ri     = (const float*)d_in[4];
    const float* Dp        = (const float*)d_in[5];
    const float* log_step  = (const float*)d_in[6];
    float* y = (float*)d_out;

    (void)in_sizes; (void)n_in; (void)out_size;

    const int KF_SMEM   = (512 + 2184 + 4368) * sizeof(float2);   // 56512
    const int CONV_SMEM = (256 + 2 * 4368) * sizeof(float2);      // 71936

    cudaFuncSetAttribute(kf_kernel,   cudaFuncAttributeMaxDynamicSharedMemorySize, KF_SMEM);
    cudaFuncSetAttribute(conv_kernel, cudaFuncAttributeMaxDynamicSharedMemorySize, CONV_SMEM);

    at_roots_kernel<<<dim3(D_MODEL, 2), 256>>>(p_ri, lambda_ri, B_ri, Ct_ri, log_step);
    kf_kernel<<<D_MODEL, 256, KF_SMEM>>>();
    conv_kernel<<<NBATCH * 64, 256, CONV_SMEM>>>(u, Dp, y);
}

// round 9
// speedup vs baseline: 1.0432x; 1.0432x over previous
#include <cuda_runtime.h>
#include <math.h>

#define D_MODEL 256
#define N_STATE 64
#define LSEQ    2048
#define L2X     4096
#define NBATCH  16

typedef unsigned long long ull;

// Scratch (no cudaMalloc allowed).
__device__ float2 g_at[D_MODEL * LSEQ];   // 4 MB
__device__ float2 g_kf[D_MODEL * L2X];    // 8 MB, NATURAL frequency order

static __device__ __forceinline__ float2 cmul(float2 a, float2 b) {
    return make_float2(a.x * b.x - a.y * b.y, a.x * b.y + a.y * b.x);
}
static __device__ __forceinline__ float2 cadd(float2 a, float2 b) {
    return make_float2(a.x + b.x, a.y + b.y);
}
static __device__ __forceinline__ float2 csub(float2 a, float2 b) {
    return make_float2(a.x - b.x, a.y - b.y);
}

static __device__ __forceinline__ void barsync(int id, int nthr) {
    asm volatile("bar.sync %0, %1;" :: "r"(id), "r"(nthr) : "memory");
}

// packed f32x2 ops (sm_103a; FFMA2 only reachable via PTX)
#define F2ADD(d,a,b)   asm("add.rn.f32x2 %0,%1,%2;"    : "=l"(d) : "l"(a), "l"(b))
#define F2MUL(d,a,b)   asm("mul.rn.f32x2 %0,%1,%2;"    : "=l"(d) : "l"(a), "l"(b))
#define F2FMA(d,a,b,c) asm("fma.rn.f32x2 %0,%1,%2,%3;" : "=l"(d) : "l"(a), "l"(b), "l"(c))
#define F2PACK(d,lo,hi) asm("mov.b64 %0,{%1,%2};" : "=l"(d) : "f"(lo), "f"(hi))
#define F2UNPK(lo,hi,v) asm("mov.b64 {%0,%1},%2;" : "=f"(lo), "=f"(hi) : "l"(v))
#define FRCP(d,a)      asm("rcp.approx.f32 %0,%1;" : "=f"(d) : "f"(a))

// Triple-pad smem addressing: conflict-free for strides 256, 16, 1.
#define PIDX(a) ((a) + ((a) >> 4) + ((a) >> 8))

// radix-16 digit reversal for N=4096 (digits 16,16,16)
static __device__ __forceinline__ int rev16(int k) {
    return ((k & 15) << 8) | (k & 240) | (k >> 8);
}

// output slot permutation of bfly16: X[q] lives in v[PERM16(q)]
#define PERM16(q) ((((q) & 3) << 2) | ((q) >> 2))

// ---------------------------------------------------------------------------
// DFT4 (INV=false: W4=-i forward; INV=true: +i)
// ---------------------------------------------------------------------------
template<bool INV>
static __device__ __forceinline__ void dft4(float2& a, float2& b, float2& c, float2& d)
{
    float2 t0 = cadd(a, c), t1 = csub(a, c), t2 = cadd(b, d), t3 = csub(b, d);
    float2 j3 = INV ? make_float2(-t3.y, t3.x) : make_float2(t3.y, -t3.x);
    a = cadd(t0, t2); c = csub(t0, t2);
    b = cadd(t1, j3); d = csub(t1, j3);
}

template<bool INV>
static __device__ __forceinline__ float2 cmulw(float2 x, float wr, float wi)
{
    return cmul(x, make_float2(wr, INV ? -wi : wi));
}

// ---------------------------------------------------------------------------
// 16-point DFT in registers. Input natural v[n]; output X[q] at v[PERM16(q)].
// ---------------------------------------------------------------------------
template<bool INV>
static __device__ __forceinline__ void bfly16(float2 v[16])
{
    const float C1 = 0.9238795325112867f, S1 = 0.3826834323650898f, R2 = 0.7071067811865476f;
    dft4<INV>(v[0], v[4], v[8],  v[12]);
    dft4<INV>(v[1], v[5], v[9],  v[13]);
    dft4<INV>(v[2], v[6], v[10], v[14]);
    dft4<INV>(v[3], v[7], v[11], v[15]);
    v[5]  = cmulw<INV>(v[5],  C1, -S1);   // W^1
    v[6]  = cmulw<INV>(v[6],  R2, -R2);   // W^2
    v[7]  = cmulw<INV>(v[7],  S1, -C1);   // W^3
    v[9]  = cmulw<INV>(v[9],  R2, -R2);   // W^2
    v[10] = cmulw<INV>(v[10], 0.f, -1.f); // W^4
    v[11] = cmulw<INV>(v[11], -R2, -R2);  // W^6
    v[13] = cmulw<INV>(v[13], S1, -C1);   // W^3
    v[14] = cmulw<INV>(v[14], -R2, -R2);  // W^6
    v[15] = cmulw<INV>(v[15], -C1,  S1);  // W^9
    dft4<INV>(v[0],  v[1],  v[2],  v[3]);
    dft4<INV>(v[4],  v[5],  v[6],  v[7]);
    dft4<INV>(v[8],  v[9],  v[10], v[11]);
    dft4<INV>(v[12], v[13], v[14], v[15]);
}

// multiply by powers of w1: FREQ=true -> v[q] *= w1^q ; else v[PERM16(q)] *= w1^q
template<bool FREQ>
static __device__ __forceinline__ void twapply16(float2 v[16], float2 w1)
{
#define TSLOT(q) (FREQ ? (q) : PERM16(q))
    float2 w2 = cmul(w1, w1);
    v[TSLOT(1)] = cmul(v[TSLOT(1)], w1);
    v[TSLOT(2)] = cmul(v[TSLOT(2)], w2);
    float2 w3 = cmul(w2, w1);
    v[TSLOT(3)] = cmul(v[TSLOT(3)], w3);
    float2 w4 = cmul(w2, w2);
    v[TSLOT(4)] = cmul(v[TSLOT(4)], w4);
    float2 w5 = cmul(w4, w1);
    v[TSLOT(5)] = cmul(v[TSLOT(5)], w5);
    float2 w6 = cmul(w4, w2);
    v[TSLOT(6)] = cmul(v[TSLOT(6)], w6);
    float2 w7 = cmul(w4, w3);
    v[TSLOT(7)] = cmul(v[TSLOT(7)], w7);
    float2 w8 = cmul(w4, w4);
    v[TSLOT(8)]  = cmul(v[TSLOT(8)],  w8);
    v[TSLOT(9)]  = cmul(v[TSLOT(9)],  cmul(w8, w1));
    v[TSLOT(10)] = cmul(v[TSLOT(10)], cmul(w8, w2));
    v[TSLOT(11)] = cmul(v[TSLOT(11)], cmul(w8, w3));
    v[TSLOT(12)] = cmul(v[TSLOT(12)], cmul(w8, w4));
    v[TSLOT(13)] = cmul(v[TSLOT(13)], cmul(w8, w5));
    v[TSLOT(14)] = cmul(v[TSLOT(14)], cmul(w8, w6));
    v[TSLOT(15)] = cmul(v[TSLOT(15)], cmul(w8, w7));
#undef TSLOT
}

// ---------------------------------------------------------------------------
// In-place radix-16 stage. Forward DIF; inverse DIT. tw[k] = W_4096^k.
// ---------------------------------------------------------------------------
template<bool INV>
static __device__ void stage16(float2* buf, const float2* __restrict__ tw,
                               int L, int NB, int gtid, int GT)
{
    const int m = L >> 4;
    const int twstep = L2X / L;
    for (int b = gtid; b < NB; b += GT) {
        int j = b & (m - 1);
        int base = ((b - j) << 4) + j;
        float2 v[16];
        #pragma unroll
        for (int r = 0; r < 16; r++) v[r] = buf[PIDX(base + m * r)];

        if (!INV) {
            bfly16<false>(v);
            if (m > 1) {
                float2 w1 = tw[j * twstep];
                twapply16<false>(v, w1);
            }
        } else {
            if (m > 1) {
                float2 w1 = tw[j * twstep]; w1.y = -w1.y;
                twapply16<true>(v, w1);
            }
            bfly16<true>(v);
        }
        #pragma unroll
        for (int q = 0; q < 16; q++) buf[PIDX(base + m * q)] = v[PERM16(q)];
    }
}

// ---------------------------------------------------------------------------
// 8-point DFT + radix-8 DIF stage (kf's 2048 = 8*16*16 first stage)
// ---------------------------------------------------------------------------
template<bool INV>
static __device__ __forceinline__ void bfly8(float2 v[8])
{
    const float t = 0.70710678118654752f;
    float2 a0 = cadd(v[0], v[4]), a4 = csub(v[0], v[4]);
    float2 a1 = cadd(v[1], v[5]), a5 = csub(v[1], v[5]);
    float2 a2 = cadd(v[2], v[6]), a6 = csub(v[2], v[6]);
    float2 a3 = cadd(v[3], v[7]), a7 = csub(v[3], v[7]);
    float2 b0 = cadd(a0, a2), b2 = csub(a0, a2);
    float2 b1 = cadd(a1, a3), b3 = csub(a1, a3);
    float2 m4b3 = INV ? make_float2(-b3.y, b3.x) : make_float2(b3.y, -b3.x);
    v[0] = cadd(b0, b1);  v[4] = csub(b0, b1);
    v[2] = cadd(b2, m4b3); v[6] = csub(b2, m4b3);
    float2 c0 = a4;
    float2 c1 = INV ? make_float2(t * (a5.x - a5.y), t * (a5.x + a5.y))
                    : make_float2(t * (a5.x + a5.y), t * (a5.y - a5.x));
    float2 c2 = INV ? make_float2(-a6.y, a6.x) : make_float2(a6.y, -a6.x);
    float2 c3 = INV ? make_float2(-t * (a7.x + a7.y), t * (a7.x - a7.y))
                    : make_float2(t * (a7.y - a7.x), -t * (a7.x + a7.y));
    float2 d0 = cadd(c0, c2), d2 = csub(c0, c2);
    float2 d1 = cadd(c1, c3), d3 = csub(c1, c3);
    float2 m4d3 = INV ? make_float2(-d3.y, d3.x) : make_float2(d3.y, -d3.x);
    v[1] = cadd(d0, d1);  v[5] = csub(d0, d1);
    v[3] = cadd(d2, m4d3); v[7] = csub(d2, m4d3);
}

template<bool INV>
static __device__ void stage8(float2* buf, const float2* __restrict__ tw,
                              int L, int NB, int gtid, int GT)
{
    int m = L >> 3;
    int twstep = L2X / L;
    for (int b = gtid; b < NB; b += GT) {
        int j = b & (m - 1);
        int base = ((b - j) << 3) + j;
        float2 v[8];
        #pragma unroll
        for (int r = 0; r < 8; r++) v[r] = buf[PIDX(base + m * r)];

        if (m > 1) {
            float2 w = tw[j * twstep];
            if (INV) w.y = -w.y;
            if (!INV) {
                bfly8<false>(v);
                float2 wq = w;
                v[1] = cmul(v[1], wq);
                #pragma unroll
                for (int q = 2; q < 8; q++) { wq = cmul(wq, w); v[q] = cmul(v[q], wq); }
            } else {
                float2 wq = w;
                v[1] = cmul(v[1], wq);
                #pragma unroll
                for (int q = 2; q < 8; q++) { wq = cmul(wq, w); v[q] = cmul(v[q], wq); }
                bfly8<true>(v);
            }
        } else {
            bfly8<INV>(v);
        }
        #pragma unroll
        for (int r = 0; r < 8; r++) buf[PIDX(base + m * r)] = v[r];
    }
}

// ---------------------------------------------------------------------------
// Stage A: at_roots via Woodbury, f32x2-packed, 2 j per thread (R6 version —
// the 4-j variant pushed regs to 102 and regressed). grid (256, 4).
// omega trig MUST be precise sincosf (MUFU sin==0 at pi -> NaN).
// ---------------------------------------------------------------------------
__global__ __launch_bounds__(256)
void at_roots_kernel(const float* __restrict__ p_ri,
                     const float* __restrict__ lambda_ri,
                     const float* __restrict__ B_ri,
                     const float* __restrict__ Ct_ri,
                     const float* __restrict__ log_step)
{
    __shared__ ull s_nlx[N_STATE], s_nly[N_STATE];
    __shared__ ull s_cbx[N_STATE], s_cby[N_STATE];
    __shared__ ull s_cpx[N_STATE], s_cpy[N_STATE];
    __shared__ ull s_pbx[N_STATE], s_pby[N_STATE];
    __shared__ ull s_pp [N_STATE];

    int d = blockIdx.x;
    int jlo = blockIdx.y * 512;
    int tid = threadIdx.x;

    if (tid < N_STATE) {
        int n = tid;
        float pr = p_ri[2 * n], pi = p_ri[2 * n + 1];
        float2 lam = make_float2(lambda_ri[2 * n], lambda_ri[2 * n + 1]);
        float2 Bv  = make_float2(B_ri[(d * N_STATE + n) * 2], B_ri[(d * N_STATE + n) * 2 + 1]);
        float2 Ctc = make_float2(Ct_ri[(d * N_STATE + n) * 2], -Ct_ri[(d * N_STATE + n) * 2 + 1]);
        float2 CtB = cmul(Ctc, Bv);
        float2 Ctp = cmul(Ctc, make_float2(pr, pi));
        float2 pB  = cmul(make_float2(pr, -pi), Bv);
        float  pp  = pr * pr + pi * pi;
        F2PACK(s_nlx[n], -lam.x, -lam.x);
        F2PACK(s_nly[n], -lam.y, -lam.y);
        F2PACK(s_cbx[n], CtB.x, CtB.x);  F2PACK(s_cby[n], CtB.y, CtB.y);
        F2PACK(s_cpx[n], Ctp.x, Ctp.x);  F2PACK(s_cpy[n], Ctp.y, Ctp.y);
        F2PACK(s_pbx[n], pB.x,  pB.x);   F2PACK(s_pby[n], pB.y,  pB.y);
        F2PACK(s_pp [n], pp,    pp);
    }
    __syncthreads();

    float tos = 2.0f * __expf(-log_step[d]);

    int j0 = jlo + 2 * tid;

    float gx[2], gy[2], ccx[2], ccy[2];
    #pragma unroll
    for (int e = 0; e < 2; e++) {
        int j = j0 + e;
        float ang = 6.283185307179586f * (float)j * (1.0f / (float)LSEQ);
        float sj, cj;
        sincosf(ang, &sj, &cj);
        float2 onep = make_float2(1.0f + cj, sj);
        float2 onem = make_float2(1.0f - cj, -sj);
        float mag = fmaxf(onep.x * onep.x + onep.y * onep.y, 1e-30f);
        float rp = 1.0f / mag;
        float2 ip = make_float2(onep.x * rp, -onep.y * rp);
        ccx[e] = 2.0f * ip.x; ccy[e] = 2.0f * ip.y;
        float2 gq = cmul(onem, ip);
        gx[e] = tos * gq.x; gy[e] = tos * gq.y;
    }
    ull gx2, gy2;
    F2PACK(gx2, gx[0], gx[1]);
    F2PACK(gy2, gy[0], gy[1]);

    ull k00x = 0, k00y = 0, k00s = 0;
    ull k01x = 0, k01y = 0, k01s = 0;
    ull k10x = 0, k10y = 0, k10s = 0;
    ull k11x = 0, k11s = 0;

    #pragma unroll 8
    for (int n = 0; n < N_STATE; n++) {
        ull dcx, dcy, m2, r, ix, t, tmp;
        F2ADD(dcx, gx2, s_nlx[n]);
        F2ADD(dcy, gy2, s_nly[n]);
        F2MUL(tmp, dcx, dcx);
        F2FMA(m2, dcy, dcy, tmp);
        float mlo, mhi, rlo, rhi;
        F2UNPK(mlo, mhi, m2);
        FRCP(rlo, mlo);
        FRCP(rhi, mhi);
        F2PACK(r, rlo, rhi);
        F2MUL(ix, dcx, r);
        F2MUL(t,  dcy, r);
        F2FMA(k00x, s_cbx[n], ix, k00x);
        F2FMA(k00x, s_cby[n], t,  k00x);
        F2FMA(k00y, s_cby[n], ix, k00y);
        F2FMA(k00s, s_cbx[n], t,  k00s);
        F2FMA(k01x, s_cpx[n], ix, k01x);
        F2FMA(k01x, s_cpy[n], t,  k01x);
        F2FMA(k01y, s_cpy[n], ix, k01y);
        F2FMA(k01s, s_cpx[n], t,  k01s);
        F2FMA(k10x, s_pbx[n], ix, k10x);
        F2FMA(k10x, s_pby[n], t,  k10x);
        F2FMA(k10y, s_pby[n], ix, k10y);
        F2FMA(k10s, s_pbx[n], t,  k10s);
        F2FMA(k11x, s_pp[n], ix, k11x);
        F2FMA(k11s, s_pp[n], t,  k11s);
    }

    float a00x[2], a00y[2], a01x[2], a01y[2], a10x[2], a10y[2], a11x[2], a11y[2];
    F2UNPK(a00x[0], a00x[1], k00x);
    { float y0,y1,s0,s1; F2UNPK(y0,y1,k00y); F2UNPK(s0,s1,k00s); a00y[0]=y0-s0; a00y[1]=y1-s1; }
    F2UNPK(a01x[0], a01x[1], k01x);
    { float y0,y1,s0,s1; F2UNPK(y0,y1,k01y); F2UNPK(s0,s1,k01s); a01y[0]=y0-s0; a01y[1]=y1-s1; }
    F2UNPK(a10x[0], a10x[1], k10x);
    { float y0,y1,s0,s1; F2UNPK(y0,y1,k10y); F2UNPK(s0,s1,k10s); a10y[0]=y0-s0; a10y[1]=y1-s1; }
    F2UNPK(a11x[0], a11x[1], k11x);
    { float s0,s1; F2UNPK(s0,s1,k11s); a11y[0]=-s0; a11y[1]=-s1; }

    float4 outv;
    #pragma unroll
    for (int e = 0; e < 2; e++) {
        float2 k00 = make_float2(a00x[e], a00y[e]);
        float2 k01 = make_float2(a01x[e], a01y[e]);
        float2 k10 = make_float2(a10x[e], a10y[e]);
        float2 den = make_float2(1.0f + a11x[e], a11y[e]);
        float rd = __fdividef(1.0f, den.x * den.x + den.y * den.y);
        float2 iden = make_float2(den.x * rd, -den.y * rd);
        float2 frac = cmul(cmul(k01, k10), iden);
        float2 res  = cmul(make_float2(ccx[e], ccy[e]), csub(k00, frac));
        if (e == 0) { outv.x = res.x; outv.y = res.y; }
        else        { outv.z = res.x; outv.w = res.y; }
    }
    *(float4*)&g_at[d * LSEQ + j0] = outv;
}

// ---------------------------------------------------------------------------
// Stage B: per channel d:
//   K = Re(DFT_2048(at_roots))/2048 ; Kf = DFT_4096(pad(K)) natural order.
// 2048 = 8*16*16; 4096 = 16^3.
// ---------------------------------------------------------------------------
__global__ void kf_kernel()
{
    extern __shared__ float2 sm[];
    float2* tw   = sm;                 // 512 (W_4096^k, k<512)
    float2* bufA = sm + 512;           // padded 2048 -> 2184
    float2* bufB = sm + 512 + 2184;    // padded 4096 -> 4368

    int d = blockIdx.x;
    int tid = threadIdx.x;
    const int T = 256;

    for (int k = tid; k < 512; k += T) {
        float s, c;
        sincosf(6.283185307179586f * (float)k * (1.0f / 4096.0f), &s, &c);
        tw[k] = make_float2(c, -s);
    }
    for (int j = tid; j < LSEQ; j += T) bufA[PIDX(j)] = g_at[d * LSEQ + j];
    __syncthreads();

    // ---- FFT-2048 forward: radices 8,16,16 ----
    stage8 <false>(bufA, tw, 2048, 256, tid, T); __syncthreads();
    stage16<false>(bufA, tw,  256, 128, tid, T); __syncthreads();
    stage16<false>(bufA, tw,   16, 128, tid, T); __syncthreads();

    // ---- pad K (un-digit-reverse: l = l0 + 8 l1 + 128 l2 -> p = 256 l0 + 16 l1 + l2)
    for (int l = tid; l < LSEQ; l += T) {
        int p = ((l & 7) << 8) | (((l >> 3) & 15) << 4) | ((l >> 7) & 15);
        bufB[PIDX(l)] = make_float2(bufA[PIDX(p)].x * (1.0f / (float)LSEQ), 0.0f);
        bufB[PIDX(l + LSEQ)] = make_float2(0.0f, 0.0f);
    }
    __syncthreads();

    // ---- FFT-4096 forward: 16^3 ----
    stage16<false>(bufB, tw, 4096, 256, tid, T); __syncthreads();
    stage16<false>(bufB, tw,  256, 256, tid, T); __syncthreads();
    stage16<false>(bufB, tw,   16, 256, tid, T); __syncthreads();

    // natural-order coalesced global write
    for (int k = tid; k < L2X; k += T)
        g_kf[d * L2X + k] = bufB[PIDX(rev16(k))];
}

// ---------------------------------------------------------------------------
// Stage C: causal FFT conv. 4 channels/block, 2 groups x 128 threads.
// First fwd stage fused with gmem load (zero-padded half folds away).
// Inverse path: 3 plain smem stages + separate epilogue (the fused store
// epilogue spilled under the 3-CTA reg budget and regressed in R7).
// ---------------------------------------------------------------------------
__global__ __launch_bounds__(256, 3)
void conv_kernel(const float* __restrict__ u,
                 const float* __restrict__ Dp,
                 float* __restrict__ y)
{
    extern __shared__ float2 sm[];
    float2* tw = sm;                          // 256 (W_4096^k, k<256)

    int tid = threadIdx.x;
    int q   = tid >> 7;                       // group 0..1
    int gt  = tid & 127;
    float2* buf = sm + 256 + q * 4368;        // padded 4096 per group

    int b  = blockIdx.x >> 6;                 // 16 batches
    int c0 = (blockIdx.x & 63) * 4 + 2 * q;   // channel pair
    int barId = 1 + q;

    if (tid < 256) {
        float s, c;
        sincosf(6.283185307179586f * (float)tid * (1.0f / 4096.0f), &s, &c);
        tw[tid] = make_float2(c, -s);
    }
    __syncthreads();

    const float* ub = u + (size_t)b * LSEQ * D_MODEL + c0;

    // ---- fused: load z = u[:,c0]+i*u[:,c0+1] (implicit 2048-zero pad) +
    // first fwd stage (L=4096, m=256). Butterfly j reads l = j + 256r, r<8
    // nonzero; upper half of the DFT16 inputs is identically zero.
    for (int j = gt; j < 256; j += 128) {
        float2 v[16];
        #pragma unroll
        for (int r = 0; r < 8; r++)
            v[r] = *(const float2*)&ub[(size_t)(j + 256 * r) * D_MODEL];
        #pragma unroll
        for (int r = 8; r < 16; r++) v[r] = make_float2(0.0f, 0.0f);
        bfly16<false>(v);
        twapply16<false>(v, tw[j]);
        #pragma unroll
        for (int p = 0; p < 16; p++) buf[PIDX(j + 256 * p)] = v[PERM16(p)];
    }
    barsync(barId, 128);

    stage16<false>(buf, tw,  256, 256, gt, 128); barsync(barId, 128);
    stage16<false>(buf, tw,   16, 256, gt, 128); barsync(barId, 128);

    // unpack packed real spectra, multiply by Kf, repack (digit-reversed smem)
    for (int k = gt; k <= 2048; k += 128) {
        int mk = (L2X - k) & (L2X - 1);
        int pk = PIDX(rev16(k));
        int pm = PIDX(rev16(mk));
        float2 Zk = buf[pk], Zm = buf[pm];
        float2 U0 = make_float2(0.5f * (Zk.x + Zm.x), 0.5f * (Zk.y - Zm.y));
        float2 U1 = make_float2(0.5f * (Zk.y + Zm.y), 0.5f * (Zm.x - Zk.x));
        float2 H0 = g_kf[(size_t)c0 * L2X + k];
        float2 H1 = g_kf[(size_t)(c0 + 1) * L2X + k];
        float2 Y0 = cmul(U0, H0);
        float2 Y1 = cmul(U1, H1);
        buf[pk] = make_float2(Y0.x - Y1.y, Y0.y + Y1.x);          // Y0 + i*Y1
        if (k != 0 && k != 2048)
            buf[pm] = make_float2(Y0.x + Y1.y, Y1.x - Y0.y);      // conj(Y0)+i*conj(Y1)
    }
    barsync(barId, 128);

    // inverse DIT (consumes digit-reversed, emits natural)
    stage16<true>(buf, tw,   16, 256, gt, 128); barsync(barId, 128);
    stage16<true>(buf, tw,  256, 256, gt, 128); barsync(barId, 128);
    stage16<true>(buf, tw, 4096, 256, gt, 128); barsync(barId, 128);

    float d0 = Dp[c0], d1 = Dp[c0 + 1];
    const float invN = 1.0f / (float)L2X;
    float* yb = y + (size_t)b * LSEQ * D_MODEL + c0;
    for (int l = gt; l < LSEQ; l += 128) {
        size_t idx = (size_t)l * D_MODEL;
        float2 uv = *(const float2*)&ub[idx];
        float2 o = make_float2(buf[PIDX(l)].x * invN + d0 * uv.x,
                               buf[PIDX(l)].y * invN + d1 * uv.y);
        *(float2*)&yb[idx] = o;
    }
}

// ---------------------------------------------------------------------------
extern "C" void kernel_launch(void* const* d_in, const int* in_sizes, int n_in,
                              void* d_out, int out_size)
{
    const float* u         = (const float*)d_in[0];
    const float* p_ri      = (const float*)d_in[1];
    const float* lambda_ri = (const float*)d_in[2];
    const float* B_ri      = (const float*)d_in[3];
    const float* Ct_ri     = (const float*)d_in[4];
    const float* Dp        = (const float*)d_in[5];
    const float* log_step  = (const float*)d_in[6];
    float* y = (float*)d_out;

    (void)in_sizes; (void)n_in; (void)out_size;

    const int KF_SMEM   = (512 + 2184 + 4368) * sizeof(float2);   // 56512
    const int CONV_SMEM = (256 + 2 * 4368) * sizeof(float2);      // 71936

    cudaFuncSetAttribute(kf_kernel,   cudaFuncAttributeMaxDynamicSharedMemorySize, KF_SMEM);
    cudaFuncSetAttribute(conv_kernel, cudaFuncAttributeMaxDynamicSharedMemorySize, CONV_SMEM);

    at_roots_kernel<<<dim3(D_MODEL, 4), 256>>>(p_ri, lambda_ri, B_ri, Ct_ri, log_step);
    kf_kernel<<<D_MODEL, 256, KF_SMEM>>>();
    conv_kernel<<<NBATCH * 64, 256, CONV_SMEM>>>(u, Dp, y);
}

// round 10
// speedup vs baseline: 1.2474x; 1.1958x over previous
#include <cuda_runtime.h>
#include <math.h>

#define D_MODEL 256
#define N_STATE 64
#define LSEQ    2048
#define L2X     4096
#define NBATCH  16

typedef unsigned long long ull;

// Scratch (no cudaMalloc allowed).
__device__ float2 g_at[D_MODEL * LSEQ];   // 4 MB
__device__ float2 g_kf[D_MODEL * L2X];    // 8 MB, NATURAL frequency order

static __device__ __forceinline__ float2 cmul(float2 a, float2 b) {
    return make_float2(a.x * b.x - a.y * b.y, a.x * b.y + a.y * b.x);
}
static __device__ __forceinline__ float2 cadd(float2 a, float2 b) {
    return make_float2(a.x + b.x, a.y + b.y);
}
static __device__ __forceinline__ float2 csub(float2 a, float2 b) {
    return make_float2(a.x - b.x, a.y - b.y);
}

static __device__ __forceinline__ void barsync(int id, int nthr) {
    asm volatile("bar.sync %0, %1;" :: "r"(id), "r"(nthr) : "memory");
}

// packed f32x2 ops (sm_103a; FFMA2 only reachable via PTX)
#define F2ADD(d,a,b)   asm("add.rn.f32x2 %0,%1,%2;"    : "=l"(d) : "l"(a), "l"(b))
#define F2MUL(d,a,b)   asm("mul.rn.f32x2 %0,%1,%2;"    : "=l"(d) : "l"(a), "l"(b))
#define F2FMA(d,a,b,c) asm("fma.rn.f32x2 %0,%1,%2,%3;" : "=l"(d) : "l"(a), "l"(b), "l"(c))
#define F2PACK(d,lo,hi) asm("mov.b64 %0,{%1,%2};" : "=l"(d) : "f"(lo), "f"(hi))
#define F2UNPK(lo,hi,v) asm("mov.b64 {%0,%1},%2;" : "=f"(lo), "=f"(hi) : "l"(v))
#define FRCP(d,a)      asm("rcp.approx.f32 %0,%1;" : "=f"(d) : "f"(a))

// Triple-pad smem addressing: conflict-free for strides 256, 16, 1.
#define PIDX(a) ((a) + ((a) >> 4) + ((a) >> 8))

// radix-16 digit reversal for N=4096 (digits 16,16,16)
static __device__ __forceinline__ int rev16(int k) {
    return ((k & 15) << 8) | (k & 240) | (k >> 8);
}

// output slot permutation of bfly16: X[q] lives in v[PERM16(q)]
#define PERM16(q) ((((q) & 3) << 2) | ((q) >> 2))

// ---------------------------------------------------------------------------
// DFT4 (INV=false: W4=-i forward; INV=true: +i)
// ---------------------------------------------------------------------------
template<bool INV>
static __device__ __forceinline__ void dft4(float2& a, float2& b, float2& c, float2& d)
{
    float2 t0 = cadd(a, c), t1 = csub(a, c), t2 = cadd(b, d), t3 = csub(b, d);
    float2 j3 = INV ? make_float2(-t3.y, t3.x) : make_float2(t3.y, -t3.x);
    a = cadd(t0, t2); c = csub(t0, t2);
    b = cadd(t1, j3); d = csub(t1, j3);
}

template<bool INV>
static __device__ __forceinline__ float2 cmulw(float2 x, float wr, float wi)
{
    return cmul(x, make_float2(wr, INV ? -wi : wi));
}

// ---------------------------------------------------------------------------
// 16-point DFT in registers. Input natural v[n]; output X[q] at v[PERM16(q)].
// ---------------------------------------------------------------------------
template<bool INV>
static __device__ __forceinline__ void bfly16(float2 v[16])
{
    const float C1 = 0.9238795325112867f, S1 = 0.3826834323650898f, R2 = 0.7071067811865476f;
    dft4<INV>(v[0], v[4], v[8],  v[12]);
    dft4<INV>(v[1], v[5], v[9],  v[13]);
    dft4<INV>(v[2], v[6], v[10], v[14]);
    dft4<INV>(v[3], v[7], v[11], v[15]);
    v[5]  = cmulw<INV>(v[5],  C1, -S1);   // W^1
    v[6]  = cmulw<INV>(v[6],  R2, -R2);   // W^2
    v[7]  = cmulw<INV>(v[7],  S1, -C1);   // W^3
    v[9]  = cmulw<INV>(v[9],  R2, -R2);   // W^2
    v[10] = cmulw<INV>(v[10], 0.f, -1.f); // W^4
    v[11] = cmulw<INV>(v[11], -R2, -R2);  // W^6
    v[13] = cmulw<INV>(v[13], S1, -C1);   // W^3
    v[14] = cmulw<INV>(v[14], -R2, -R2);  // W^6
    v[15] = cmulw<INV>(v[15], -C1,  S1);  // W^9
    dft4<INV>(v[0],  v[1],  v[2],  v[3]);
    dft4<INV>(v[4],  v[5],  v[6],  v[7]);
    dft4<INV>(v[8],  v[9],  v[10], v[11]);
    dft4<INV>(v[12], v[13], v[14], v[15]);
}

// multiply by powers of w1: FREQ=true -> v[q] *= w1^q ; else v[PERM16(q)] *= w1^q
template<bool FREQ>
static __device__ __forceinline__ void twapply16(float2 v[16], float2 w1)
{
#define TSLOT(q) (FREQ ? (q) : PERM16(q))
    float2 w2 = cmul(w1, w1);
    v[TSLOT(1)] = cmul(v[TSLOT(1)], w1);
    v[TSLOT(2)] = cmul(v[TSLOT(2)], w2);
    float2 w3 = cmul(w2, w1);
    v[TSLOT(3)] = cmul(v[TSLOT(3)], w3);
    float2 w4 = cmul(w2, w2);
    v[TSLOT(4)] = cmul(v[TSLOT(4)], w4);
    float2 w5 = cmul(w4, w1);
    v[TSLOT(5)] = cmul(v[TSLOT(5)], w5);
    float2 w6 = cmul(w4, w2);
    v[TSLOT(6)] = cmul(v[TSLOT(6)], w6);
    float2 w7 = cmul(w4, w3);
    v[TSLOT(7)] = cmul(v[TSLOT(7)], w7);
    float2 w8 = cmul(w4, w4);
    v[TSLOT(8)]  = cmul(v[TSLOT(8)],  w8);
    v[TSLOT(9)]  = cmul(v[TSLOT(9)],  cmul(w8, w1));
    v[TSLOT(10)] = cmul(v[TSLOT(10)], cmul(w8, w2));
    v[TSLOT(11)] = cmul(v[TSLOT(11)], cmul(w8, w3));
    v[TSLOT(12)] = cmul(v[TSLOT(12)], cmul(w8, w4));
    v[TSLOT(13)] = cmul(v[TSLOT(13)], cmul(w8, w5));
    v[TSLOT(14)] = cmul(v[TSLOT(14)], cmul(w8, w6));
    v[TSLOT(15)] = cmul(v[TSLOT(15)], cmul(w8, w7));
#undef TSLOT
}

// ---------------------------------------------------------------------------
// In-place radix-16 stage. Forward DIF; inverse DIT. tw[k] = W_4096^k.
// ---------------------------------------------------------------------------
template<bool INV>
static __device__ void stage16(float2* buf, const float2* __restrict__ tw,
                               int L, int NB, int gtid, int GT)
{
    const int m = L >> 4;
    const int twstep = L2X / L;
    for (int b = gtid; b < NB; b += GT) {
        int j = b & (m - 1);
        int base = ((b - j) << 4) + j;
        float2 v[16];
        #pragma unroll
        for (int r = 0; r < 16; r++) v[r] = buf[PIDX(base + m * r)];

        if (!INV) {
            bfly16<false>(v);
            if (m > 1) {
                float2 w1 = tw[j * twstep];
                twapply16<false>(v, w1);
            }
        } else {
            if (m > 1) {
                float2 w1 = tw[j * twstep]; w1.y = -w1.y;
                twapply16<true>(v, w1);
            }
            bfly16<true>(v);
        }
        #pragma unroll
        for (int q = 0; q < 16; q++) buf[PIDX(base + m * q)] = v[PERM16(q)];
    }
}

// ---------------------------------------------------------------------------
// 8-point DFT + radix-8 DIF stage (kf's 2048 = 8*16*16 first stage)
// ---------------------------------------------------------------------------
template<bool INV>
static __device__ __forceinline__ void bfly8(float2 v[8])
{
    const float t = 0.70710678118654752f;
    float2 a0 = cadd(v[0], v[4]), a4 = csub(v[0], v[4]);
    float2 a1 = cadd(v[1], v[5]), a5 = csub(v[1], v[5]);
    float2 a2 = cadd(v[2], v[6]), a6 = csub(v[2], v[6]);
    float2 a3 = cadd(v[3], v[7]), a7 = csub(v[3], v[7]);
    float2 b0 = cadd(a0, a2), b2 = csub(a0, a2);
    float2 b1 = cadd(a1, a3), b3 = csub(a1, a3);
    float2 m4b3 = INV ? make_float2(-b3.y, b3.x) : make_float2(b3.y, -b3.x);
    v[0] = cadd(b0, b1);  v[4] = csub(b0, b1);
    v[2] = cadd(b2, m4b3); v[6] = csub(b2, m4b3);
    float2 c0 = a4;
    float2 c1 = INV ? make_float2(t * (a5.x - a5.y), t * (a5.x + a5.y))
                    : make_float2(t * (a5.x + a5.y), t * (a5.y - a5.x));
    float2 c2 = INV ? make_float2(-a6.y, a6.x) : make_float2(a6.y, -a6.x);
    float2 c3 = INV ? make_float2(-t * (a7.x + a7.y), t * (a7.x - a7.y))
                    : make_float2(t * (a7.y - a7.x), -t * (a7.x + a7.y));
    float2 d0 = cadd(c0, c2), d2 = csub(c0, c2);
    float2 d1 = cadd(c1, c3), d3 = csub(c1, c3);
    float2 m4d3 = INV ? make_float2(-d3.y, d3.x) : make_float2(d3.y, -d3.x);
    v[1] = cadd(d0, d1);  v[5] = csub(d0, d1);
    v[3] = cadd(d2, m4d3); v[7] = csub(d2, m4d3);
}

template<bool INV>
static __device__ void stage8(float2* buf, const float2* __restrict__ tw,
                              int L, int NB, int gtid, int GT)
{
    int m = L >> 3;
    int twstep = L2X / L;
    for (int b = gtid; b < NB; b += GT) {
        int j = b & (m - 1);
        int base = ((b - j) << 3) + j;
        float2 v[8];
        #pragma unroll
        for (int r = 0; r < 8; r++) v[r] = buf[PIDX(base + m * r)];

        if (m > 1) {
            float2 w = tw[j * twstep];
            if (INV) w.y = -w.y;
            if (!INV) {
                bfly8<false>(v);
                float2 wq = w;
                v[1] = cmul(v[1], wq);
                #pragma unroll
                for (int q = 2; q < 8; q++) { wq = cmul(wq, w); v[q] = cmul(v[q], wq); }
            } else {
                float2 wq = w;
                v[1] = cmul(v[1], wq);
                #pragma unroll
                for (int q = 2; q < 8; q++) { wq = cmul(wq, w); v[q] = cmul(v[q], wq); }
                bfly8<true>(v);
            }
        } else {
            bfly8<INV>(v);
        }
        #pragma unroll
        for (int r = 0; r < 8; r++) buf[PIDX(base + m * r)] = v[r];
    }
}

// ---------------------------------------------------------------------------
// Stage A: at_roots via Woodbury, f32x2-packed, 2 j per thread. grid (256,4).
// omega trig MUST be precise sincosf (MUFU sin==0 at pi -> NaN).
// ---------------------------------------------------------------------------
__global__ __launch_bounds__(256)
void at_roots_kernel(const float* __restrict__ p_ri,
                     const float* __restrict__ lambda_ri,
                     const float* __restrict__ B_ri,
                     const float* __restrict__ Ct_ri,
                     const float* __restrict__ log_step)
{
    __shared__ ull s_nlx[N_STATE], s_nly[N_STATE];
    __shared__ ull s_cbx[N_STATE], s_cby[N_STATE];
    __shared__ ull s_cpx[N_STATE], s_cpy[N_STATE];
    __shared__ ull s_pbx[N_STATE], s_pby[N_STATE];
    __shared__ ull s_pp [N_STATE];

    int d = blockIdx.x;
    int jlo = blockIdx.y * 512;
    int tid = threadIdx.x;

    if (tid < N_STATE) {
        int n = tid;
        float pr = p_ri[2 * n], pi = p_ri[2 * n + 1];
        float2 lam = make_float2(lambda_ri[2 * n], lambda_ri[2 * n + 1]);
        float2 Bv  = make_float2(B_ri[(d * N_STATE + n) * 2], B_ri[(d * N_STATE + n) * 2 + 1]);
        float2 Ctc = make_float2(Ct_ri[(d * N_STATE + n) * 2], -Ct_ri[(d * N_STATE + n) * 2 + 1]);
        float2 CtB = cmul(Ctc, Bv);
        float2 Ctp = cmul(Ctc, make_float2(pr, pi));
        float2 pB  = cmul(make_float2(pr, -pi), Bv);
        float  pp  = pr * pr + pi * pi;
        F2PACK(s_nlx[n], -lam.x, -lam.x);
        F2PACK(s_nly[n], -lam.y, -lam.y);
        F2PACK(s_cbx[n], CtB.x, CtB.x);  F2PACK(s_cby[n], CtB.y, CtB.y);
        F2PACK(s_cpx[n], Ctp.x, Ctp.x);  F2PACK(s_cpy[n], Ctp.y, Ctp.y);
        F2PACK(s_pbx[n], pB.x,  pB.x);   F2PACK(s_pby[n], pB.y,  pB.y);
        F2PACK(s_pp [n], pp,    pp);
    }
    __syncthreads();

    float tos = 2.0f * __expf(-log_step[d]);

    int j0 = jlo + 2 * tid;

    float gx[2], gy[2], ccx[2], ccy[2];
    #pragma unroll
    for (int e = 0; e < 2; e++) {
        int j = j0 + e;
        float ang = 6.283185307179586f * (float)j * (1.0f / (float)LSEQ);
        float sj, cj;
        sincosf(ang, &sj, &cj);
        float2 onep = make_float2(1.0f + cj, sj);
        float2 onem = make_float2(1.0f - cj, -sj);
        float mag = fmaxf(onep.x * onep.x + onep.y * onep.y, 1e-30f);
        float rp = 1.0f / mag;
        float2 ip = make_float2(onep.x * rp, -onep.y * rp);
        ccx[e] = 2.0f * ip.x; ccy[e] = 2.0f * ip.y;
        float2 gq = cmul(onem, ip);
        gx[e] = tos * gq.x; gy[e] = tos * gq.y;
    }
    ull gx2, gy2;
    F2PACK(gx2, gx[0], gx[1]);
    F2PACK(gy2, gy[0], gy[1]);

    ull k00x = 0, k00y = 0, k00s = 0;
    ull k01x = 0, k01y = 0, k01s = 0;
    ull k10x = 0, k10y = 0, k10s = 0;
    ull k11x = 0, k11s = 0;

    #pragma unroll 8
    for (int n = 0; n < N_STATE; n++) {
        ull dcx, dcy, m2, r, ix, t, tmp;
        F2ADD(dcx, gx2, s_nlx[n]);
        F2ADD(dcy, gy2, s_nly[n]);
        F2MUL(tmp, dcx, dcx);
        F2FMA(m2, dcy, dcy, tmp);
        float mlo, mhi, rlo, rhi;
        F2UNPK(mlo, mhi, m2);
        FRCP(rlo, mlo);
        FRCP(rhi, mhi);
        F2PACK(r, rlo, rhi);
        F2MUL(ix, dcx, r);
        F2MUL(t,  dcy, r);
        F2FMA(k00x, s_cbx[n], ix, k00x);
        F2FMA(k00x, s_cby[n], t,  k00x);
        F2FMA(k00y, s_cby[n], ix, k00y);
        F2FMA(k00s, s_cbx[n], t,  k00s);
        F2FMA(k01x, s_cpx[n], ix, k01x);
        F2FMA(k01x, s_cpy[n], t,  k01x);
        F2FMA(k01y, s_cpy[n], ix, k01y);
        F2FMA(k01s, s_cpx[n], t,  k01s);
        F2FMA(k10x, s_pbx[n], ix, k10x);
        F2FMA(k10x, s_pby[n], t,  k10x);
        F2FMA(k10y, s_pby[n], ix, k10y);
        F2FMA(k10s, s_pbx[n], t,  k10s);
        F2FMA(k11x, s_pp[n], ix, k11x);
        F2FMA(k11s, s_pp[n], t,  k11s);
    }

    float a00x[2], a00y[2], a01x[2], a01y[2], a10x[2], a10y[2], a11x[2], a11y[2];
    F2UNPK(a00x[0], a00x[1], k00x);
    { float y0,y1,s0,s1; F2UNPK(y0,y1,k00y); F2UNPK(s0,s1,k00s); a00y[0]=y0-s0; a00y[1]=y1-s1; }
    F2UNPK(a01x[0], a01x[1], k01x);
    { float y0,y1,s0,s1; F2UNPK(y0,y1,k01y); F2UNPK(s0,s1,k01s); a01y[0]=y0-s0; a01y[1]=y1-s1; }
    F2UNPK(a10x[0], a10x[1], k10x);
    { float y0,y1,s0,s1; F2UNPK(y0,y1,k10y); F2UNPK(s0,s1,k10s); a10y[0]=y0-s0; a10y[1]=y1-s1; }
    F2UNPK(a11x[0], a11x[1], k11x);
    { float s0,s1; F2UNPK(s0,s1,k11s); a11y[0]=-s0; a11y[1]=-s1; }

    float4 outv;
    #pragma unroll
    for (int e = 0; e < 2; e++) {
        float2 k00 = make_float2(a00x[e], a00y[e]);
        float2 k01 = make_float2(a01x[e], a01y[e]);
        float2 k10 = make_float2(a10x[e], a10y[e]);
        float2 den = make_float2(1.0f + a11x[e], a11y[e]);
        float rd = __fdividef(1.0f, den.x * den.x + den.y * den.y);
        float2 iden = make_float2(den.x * rd, -den.y * rd);
        float2 frac = cmul(cmul(k01, k10), iden);
        float2 res  = cmul(make_float2(ccx[e], ccy[e]), csub(k00, frac));
        if (e == 0) { outv.x = res.x; outv.y = res.y; }
        else        { outv.z = res.x; outv.w = res.y; }
    }
    *(float4*)&g_at[d * LSEQ + j0] = outv;
}

// ---------------------------------------------------------------------------
// Stage B: per channel d:
//   K = Re(DFT_2048(at_roots))/2048 ; Kf = DFT_4096(pad(K)) natural order.
// 2048 = 8*16*16; 4096 = 16^3.
// ---------------------------------------------------------------------------
__global__ void kf_kernel()
{
    extern __shared__ float2 sm[];
    float2* tw   = sm;                 // 512 (W_4096^k, k<512)
    float2* bufA = sm + 512;           // padded 2048 -> 2184
    float2* bufB = sm + 512 + 2184;    // padded 4096 -> 4368

    int d = blockIdx.x;
    int tid = threadIdx.x;
    const int T = 256;

    for (int k = tid; k < 512; k += T) {
        float s, c;
        sincosf(6.283185307179586f * (float)k * (1.0f / 4096.0f), &s, &c);
        tw[k] = make_float2(c, -s);
    }
    for (int j = tid; j < LSEQ; j += T) bufA[PIDX(j)] = g_at[d * LSEQ + j];
    __syncthreads();

    // ---- FFT-2048 forward: radices 8,16,16 ----
    stage8 <false>(bufA, tw, 2048, 256, tid, T); __syncthreads();
    stage16<false>(bufA, tw,  256, 128, tid, T); __syncthreads();
    stage16<false>(bufA, tw,   16, 128, tid, T); __syncthreads();

    // ---- pad K (un-digit-reverse: l = l0 + 8 l1 + 128 l2 -> p = 256 l0 + 16 l1 + l2)
    for (int l = tid; l < LSEQ; l += T) {
        int p = ((l & 7) << 8) | (((l >> 3) & 15) << 4) | ((l >> 7) & 15);
        bufB[PIDX(l)] = make_float2(bufA[PIDX(p)].x * (1.0f / (float)LSEQ), 0.0f);
        bufB[PIDX(l + LSEQ)] = make_float2(0.0f, 0.0f);
    }
    __syncthreads();

    // ---- FFT-4096 forward: 16^3 ----
    stage16<false>(bufB, tw, 4096, 256, tid, T); __syncthreads();
    stage16<false>(bufB, tw,  256, 256, tid, T); __syncthreads();
    stage16<false>(bufB, tw,   16, 256, tid, T); __syncthreads();

    // natural-order coalesced global write
    for (int k = tid; k < L2X; k += T)
        g_kf[d * L2X + k] = bufB[PIDX(rev16(k))];
}

// ---------------------------------------------------------------------------
// Stage C: causal FFT conv. 4 consecutive channels per block, 2 FFT groups
// of 128 threads. Gmem touched ONLY via block-wide float4 (16B) loops:
// one float4 per l covers both groups' channel pairs -> halves DRAM sector
// traffic vs per-group float2 access (8B of a 32B sector -> 16B of 32B).
// ---------------------------------------------------------------------------
__global__ __launch_bounds__(256, 3)
void conv_kernel(const float* __restrict__ u,
                 const float* __restrict__ Dp,
                 float* __restrict__ y)
{
    extern __shared__ float2 sm[];
    float2* tw   = sm;                        // 256 (W_4096^k, k<256)
    float2* buf0 = sm + 256;                  // group 0 buffer (padded 4096)
    float2* buf1 = sm + 256 + 4368;           // group 1 buffer

    int tid = threadIdx.x;
    int q   = tid >> 7;                       // group 0..1
    int gt  = tid & 127;
    float2* buf = q ? buf1 : buf0;

    int b  = blockIdx.x >> 6;                 // 16 batches
    int cb = (blockIdx.x & 63) * 4;           // block's 4-channel base
    int c0 = cb + 2 * q;                      // this group's channel pair
    int barId = 1 + q;

    if (tid < 256) {
        float s, c;
        sincosf(6.283185307179586f * (float)tid * (1.0f / 4096.0f), &s, &c);
        tw[tid] = make_float2(c, -s);
    }

    const float4* ub4 = (const float4*)(u + (size_t)b * LSEQ * D_MODEL + cb);
    float4*       yb4 = (float4*)(y + (size_t)b * LSEQ * D_MODEL + cb);

    // ---- block-wide coalesced-ish load: one 16B ld covers both groups ----
    for (int l = tid; l < LSEQ; l += 256) {
        float4 f = ub4[(size_t)l * (D_MODEL / 4)];
        buf0[PIDX(l)] = make_float2(f.x, f.y);
        buf1[PIDX(l)] = make_float2(f.z, f.w);
    }
    for (int l = LSEQ + tid; l < L2X; l += 256) {
        buf0[PIDX(l)] = make_float2(0.0f, 0.0f);
        buf1[PIDX(l)] = make_float2(0.0f, 0.0f);
    }
    __syncthreads();

    // forward DIF: 16^3 (per group)
    stage16<false>(buf, tw, 4096, 256, gt, 128); barsync(barId, 128);
    stage16<false>(buf, tw,  256, 256, gt, 128); barsync(barId, 128);
    stage16<false>(buf, tw,   16, 256, gt, 128); barsync(barId, 128);

    // unpack packed real spectra, multiply by Kf, repack (digit-reversed smem)
    for (int k = gt; k <= 2048; k += 128) {
        int mk = (L2X - k) & (L2X - 1);
        int pk = PIDX(rev16(k));
        int pm = PIDX(rev16(mk));
        float2 Zk = buf[pk], Zm = buf[pm];
        float2 U0 = make_float2(0.5f * (Zk.x + Zm.x), 0.5f * (Zk.y - Zm.y));
        float2 U1 = make_float2(0.5f * (Zk.y + Zm.y), 0.5f * (Zm.x - Zk.x));
        float2 H0 = g_kf[(size_t)c0 * L2X + k];
        float2 H1 = g_kf[(size_t)(c0 + 1) * L2X + k];
        float2 Y0 = cmul(U0, H0);
        float2 Y1 = cmul(U1, H1);
        buf[pk] = make_float2(Y0.x - Y1.y, Y0.y + Y1.x);          // Y0 + i*Y1
        if (k != 0 && k != 2048)
            buf[pm] = make_float2(Y0.x + Y1.y, Y1.x - Y0.y);      // conj(Y0)+i*conj(Y1)
    }
    barsync(barId, 128);

    // inverse DIT (consumes digit-reversed, emits natural)
    stage16<true>(buf, tw,   16, 256, gt, 128); barsync(barId, 128);
    stage16<true>(buf, tw,  256, 256, gt, 128); barsync(barId, 128);
    stage16<true>(buf, tw, 4096, 256, gt, 128);
    __syncthreads();   // join both groups before block-wide epilogue

    // ---- block-wide epilogue: one 16B ld (u) + one 16B st (y) per l ----
    float4 dp4 = *(const float4*)&Dp[cb];
    const float invN = 1.0f / (float)L2X;
    for (int l = tid; l < LSEQ; l += 256) {
        float4 uv = ub4[(size_t)l * (D_MODEL / 4)];
        float2 r0 = buf0[PIDX(l)];
        float2 r1 = buf1[PIDX(l)];
        float4 o;
        o.x = r0.x * invN + dp4.x * uv.x;
        o.y = r0.y * invN + dp4.y * uv.y;
        o.z = r1.x * invN + dp4.z * uv.z;
        o.w = r1.y * invN + dp4.w * uv.w;
        yb4[(size_t)l * (D_MODEL / 4)] = o;
    }
}

// ---------------------------------------------------------------------------
extern "C" void kernel_launch(void* const* d_in, const int* in_sizes, int n_in,
                              void* d_out, int out_size)
{
    const float* u         = (const float*)d_in[0];
    const float* p_ri      = (const float*)d_in[1];
    const float* lambda_ri = (const float*)d_in[2];
    const float* B_ri      = (const float*)d_in[3];
    const float* Ct_ri     = (const float*)d_in[4];
    const float* Dp        = (const float*)d_in[5];
    const float* log_step  = (const float*)d_in[6];
    float* y = (float*)d_out;

    (void)in_sizes; (void)n_in; (void)out_size;

    const int KF_SMEM   = (512 + 2184 + 4368) * sizeof(float2);   // 56512
    const int CONV_SMEM = (256 + 2 * 4368) * sizeof(float2);      // 71936

    cudaFuncSetAttribute(kf_kernel,   cudaFuncAttributeMaxDynamicSharedMemorySize, KF_SMEM);
    cudaFuncSetAttribute(conv_kernel, cudaFuncAttributeMaxDynamicSharedMemorySize, CONV_SMEM);

    at_roots_kernel<<<dim3(D_MODEL, 4), 256>>>(p_ri, lambda_ri, B_ri, Ct_ri, log_step);
    kf_kernel<<<D_MODEL, 256, KF_SMEM>>>();
    conv_kernel<<<NBATCH * 64, 256, CONV_SMEM>>>(u, Dp, y);
}

// round 11
// speedup vs baseline: 1.3845x; 1.1099x over previous
#include <cuda_runtime.h>
#include <math.h>

#define D_MODEL 256
#define N_STATE 64
#define LSEQ    2048
#define L2X     4096
#define NBATCH  16

typedef unsigned long long ull;

// Scratch (no cudaMalloc allowed).
__device__ float2 g_at[D_MODEL * LSEQ];   // 4 MB
__device__ float2 g_kf[D_MODEL * L2X];    // 8 MB, NATURAL frequency order

static __device__ __forceinline__ float2 cmul(float2 a, float2 b) {
    return make_float2(a.x * b.x - a.y * b.y, a.x * b.y + a.y * b.x);
}
static __device__ __forceinline__ float2 cadd(float2 a, float2 b) {
    return make_float2(a.x + b.x, a.y + b.y);
}
static __device__ __forceinline__ float2 csub(float2 a, float2 b) {
    return make_float2(a.x - b.x, a.y - b.y);
}

static __device__ __forceinline__ void barsync(int id, int nthr) {
    asm volatile("bar.sync %0, %1;" :: "r"(id), "r"(nthr) : "memory");
}

// packed f32x2 ops (sm_103a; FFMA2 only reachable via PTX)
#define F2ADD(d,a,b)   asm("add.rn.f32x2 %0,%1,%2;"    : "=l"(d) : "l"(a), "l"(b))
#define F2MUL(d,a,b)   asm("mul.rn.f32x2 %0,%1,%2;"    : "=l"(d) : "l"(a), "l"(b))
#define F2FMA(d,a,b,c) asm("fma.rn.f32x2 %0,%1,%2,%3;" : "=l"(d) : "l"(a), "l"(b), "l"(c))
#define F2PACK(d,lo,hi) asm("mov.b64 %0,{%1,%2};" : "=l"(d) : "f"(lo), "f"(hi))
#define F2UNPK(lo,hi,v) asm("mov.b64 {%0,%1},%2;" : "=f"(lo), "=f"(hi) : "l"(v))
#define FRCP(d,a)      asm("rcp.approx.f32 %0,%1;" : "=f"(d) : "f"(a))

// Triple-pad smem addressing: conflict-free for strides 256, 16, 1.
#define PIDX(a) ((a) + ((a) >> 4) + ((a) >> 8))

// radix-16 digit reversal for N=4096 (digits 16,16,16)
static __device__ __forceinline__ int rev16(int k) {
    return ((k & 15) << 8) | (k & 240) | (k >> 8);
}

// output slot permutation of bfly16: X[q] lives in v[PERM16(q)]
#define PERM16(q) ((((q) & 3) << 2) | ((q) >> 2))

// ---------------------------------------------------------------------------
// DFT4 (INV=false: W4=-i forward; INV=true: +i)
// ---------------------------------------------------------------------------
template<bool INV>
static __device__ __forceinline__ void dft4(float2& a, float2& b, float2& c, float2& d)
{
    float2 t0 = cadd(a, c), t1 = csub(a, c), t2 = cadd(b, d), t3 = csub(b, d);
    float2 j3 = INV ? make_float2(-t3.y, t3.x) : make_float2(t3.y, -t3.x);
    a = cadd(t0, t2); c = csub(t0, t2);
    b = cadd(t1, j3); d = csub(t1, j3);
}

template<bool INV>
static __device__ __forceinline__ float2 cmulw(float2 x, float wr, float wi)
{
    return cmul(x, make_float2(wr, INV ? -wi : wi));
}

// ---------------------------------------------------------------------------
// 16-point DFT in registers. Input natural v[n]; output X[q] at v[PERM16(q)].
// ---------------------------------------------------------------------------
template<bool INV>
static __device__ __forceinline__ void bfly16(float2 v[16])
{
    const float C1 = 0.9238795325112867f, S1 = 0.3826834323650898f, R2 = 0.7071067811865476f;
    dft4<INV>(v[0], v[4], v[8],  v[12]);
    dft4<INV>(v[1], v[5], v[9],  v[13]);
    dft4<INV>(v[2], v[6], v[10], v[14]);
    dft4<INV>(v[3], v[7], v[11], v[15]);
    v[5]  = cmulw<INV>(v[5],  C1, -S1);   // W^1
    v[6]  = cmulw<INV>(v[6],  R2, -R2);   // W^2
    v[7]  = cmulw<INV>(v[7],  S1, -C1);   // W^3
    v[9]  = cmulw<INV>(v[9],  R2, -R2);   // W^2
    v[10] = cmulw<INV>(v[10], 0.f, -1.f); // W^4
    v[11] = cmulw<INV>(v[11], -R2, -R2);  // W^6
    v[13] = cmulw<INV>(v[13], S1, -C1);   // W^3
    v[14] = cmulw<INV>(v[14], -R2, -R2);  // W^6
    v[15] = cmulw<INV>(v[15], -C1,  S1);  // W^9
    dft4<INV>(v[0],  v[1],  v[2],  v[3]);
    dft4<INV>(v[4],  v[5],  v[6],  v[7]);
    dft4<INV>(v[8],  v[9],  v[10], v[11]);
    dft4<INV>(v[12], v[13], v[14], v[15]);
}

// multiply by powers of w1: FREQ=true -> v[q] *= w1^q ; else v[PERM16(q)] *= w1^q
template<bool FREQ>
static __device__ __forceinline__ void twapply16(float2 v[16], float2 w1)
{
#define TSLOT(q) (FREQ ? (q) : PERM16(q))
    float2 w2 = cmul(w1, w1);
    v[TSLOT(1)] = cmul(v[TSLOT(1)], w1);
    v[TSLOT(2)] = cmul(v[TSLOT(2)], w2);
    float2 w3 = cmul(w2, w1);
    v[TSLOT(3)] = cmul(v[TSLOT(3)], w3);
    float2 w4 = cmul(w2, w2);
    v[TSLOT(4)] = cmul(v[TSLOT(4)], w4);
    float2 w5 = cmul(w4, w1);
    v[TSLOT(5)] = cmul(v[TSLOT(5)], w5);
    float2 w6 = cmul(w4, w2);
    v[TSLOT(6)] = cmul(v[TSLOT(6)], w6);
    float2 w7 = cmul(w4, w3);
    v[TSLOT(7)] = cmul(v[TSLOT(7)], w7);
    float2 w8 = cmul(w4, w4);
    v[TSLOT(8)]  = cmul(v[TSLOT(8)],  w8);
    v[TSLOT(9)]  = cmul(v[TSLOT(9)],  cmul(w8, w1));
    v[TSLOT(10)] = cmul(v[TSLOT(10)], cmul(w8, w2));
    v[TSLOT(11)] = cmul(v[TSLOT(11)], cmul(w8, w3));
    v[TSLOT(12)] = cmul(v[TSLOT(12)], cmul(w8, w4));
    v[TSLOT(13)] = cmul(v[TSLOT(13)], cmul(w8, w5));
    v[TSLOT(14)] = cmul(v[TSLOT(14)], cmul(w8, w6));
    v[TSLOT(15)] = cmul(v[TSLOT(15)], cmul(w8, w7));
#undef TSLOT
}

// ---------------------------------------------------------------------------
// In-place radix-16 stage. Forward DIF; inverse DIT. tw[k] = W_4096^k.
// ---------------------------------------------------------------------------
template<bool INV>
static __device__ void stage16(float2* buf, const float2* __restrict__ tw,
                               int L, int NB, int gtid, int GT)
{
    const int m = L >> 4;
    const int twstep = L2X / L;
    for (int b = gtid; b < NB; b += GT) {
        int j = b & (m - 1);
        int base = ((b - j) << 4) + j;
        float2 v[16];
        #pragma unroll
        for (int r = 0; r < 16; r++) v[r] = buf[PIDX(base + m * r)];

        if (!INV) {
            bfly16<false>(v);
            if (m > 1) {
                float2 w1 = tw[j * twstep];
                twapply16<false>(v, w1);
            }
        } else {
            if (m > 1) {
                float2 w1 = tw[j * twstep]; w1.y = -w1.y;
                twapply16<true>(v, w1);
            }
            bfly16<true>(v);
        }
        #pragma unroll
        for (int q = 0; q < 16; q++) buf[PIDX(base + m * q)] = v[PERM16(q)];
    }
}

// ---------------------------------------------------------------------------
// 8-point DFT + radix-8 DIF stage (kf's 2048 = 8*16*16 first stage)
// ---------------------------------------------------------------------------
template<bool INV>
static __device__ __forceinline__ void bfly8(float2 v[8])
{
    const float t = 0.70710678118654752f;
    float2 a0 = cadd(v[0], v[4]), a4 = csub(v[0], v[4]);
    float2 a1 = cadd(v[1], v[5]), a5 = csub(v[1], v[5]);
    float2 a2 = cadd(v[2], v[6]), a6 = csub(v[2], v[6]);
    float2 a3 = cadd(v[3], v[7]), a7 = csub(v[3], v[7]);
    float2 b0 = cadd(a0, a2), b2 = csub(a0, a2);
    float2 b1 = cadd(a1, a3), b3 = csub(a1, a3);
    float2 m4b3 = INV ? make_float2(-b3.y, b3.x) : make_float2(b3.y, -b3.x);
    v[0] = cadd(b0, b1);  v[4] = csub(b0, b1);
    v[2] = cadd(b2, m4b3); v[6] = csub(b2, m4b3);
    float2 c0 = a4;
    float2 c1 = INV ? make_float2(t * (a5.x - a5.y), t * (a5.x + a5.y))
                    : make_float2(t * (a5.x + a5.y), t * (a5.y - a5.x));
    float2 c2 = INV ? make_float2(-a6.y, a6.x) : make_float2(a6.y, -a6.x);
    float2 c3 = INV ? make_float2(-t * (a7.x + a7.y), t * (a7.x - a7.y))
                    : make_float2(t * (a7.y - a7.x), -t * (a7.x + a7.y));
    float2 d0 = cadd(c0, c2), d2 = csub(c0, c2);
    float2 d1 = cadd(c1, c3), d3 = csub(c1, c3);
    float2 m4d3 = INV ? make_float2(-d3.y, d3.x) : make_float2(d3.y, -d3.x);
    v[1] = cadd(d0, d1);  v[5] = csub(d0, d1);
    v[3] = cadd(d2, m4d3); v[7] = csub(d2, m4d3);
}

template<bool INV>
static __device__ void stage8(float2* buf, const float2* __restrict__ tw,
                              int L, int NB, int gtid, int GT)
{
    int m = L >> 3;
    int twstep = L2X / L;
    for (int b = gtid; b < NB; b += GT) {
        int j = b & (m - 1);
        int base = ((b - j) << 3) + j;
        float2 v[8];
        #pragma unroll
        for (int r = 0; r < 8; r++) v[r] = buf[PIDX(base + m * r)];

        if (m > 1) {
            float2 w = tw[j * twstep];
            if (INV) w.y = -w.y;
            if (!INV) {
                bfly8<false>(v);
                float2 wq = w;
                v[1] = cmul(v[1], wq);
                #pragma unroll
                for (int q = 2; q < 8; q++) { wq = cmul(wq, w); v[q] = cmul(v[q], wq); }
            } else {
                float2 wq = w;
                v[1] = cmul(v[1], wq);
                #pragma unroll
                for (int q = 2; q < 8; q++) { wq = cmul(wq, w); v[q] = cmul(v[q], wq); }
                bfly8<true>(v);
            }
        } else {
            bfly8<INV>(v);
        }
        #pragma unroll
        for (int r = 0; r < 8; r++) buf[PIDX(base + m * r)] = v[r];
    }
}

// ---------------------------------------------------------------------------
// Stage A: at_roots via Woodbury, f32x2-packed, 2 j per thread. grid (256,4).
// omega trig MUST be precise sincosf (MUFU sin==0 at pi -> NaN).
// ---------------------------------------------------------------------------
__global__ __launch_bounds__(256)
void at_roots_kernel(const float* __restrict__ p_ri,
                     const float* __restrict__ lambda_ri,
                     const float* __restrict__ B_ri,
                     const float* __restrict__ Ct_ri,
                     const float* __restrict__ log_step)
{
    __shared__ ull s_nlx[N_STATE], s_nly[N_STATE];
    __shared__ ull s_cbx[N_STATE], s_cby[N_STATE];
    __shared__ ull s_cpx[N_STATE], s_cpy[N_STATE];
    __shared__ ull s_pbx[N_STATE], s_pby[N_STATE];
    __shared__ ull s_pp [N_STATE];

    int d = blockIdx.x;
    int jlo = blockIdx.y * 512;
    int tid = threadIdx.x;

    if (tid < N_STATE) {
        int n = tid;
        float pr = p_ri[2 * n], pi = p_ri[2 * n + 1];
        float2 lam = make_float2(lambda_ri[2 * n], lambda_ri[2 * n + 1]);
        float2 Bv  = make_float2(B_ri[(d * N_STATE + n) * 2], B_ri[(d * N_STATE + n) * 2 + 1]);
        float2 Ctc = make_float2(Ct_ri[(d * N_STATE + n) * 2], -Ct_ri[(d * N_STATE + n) * 2 + 1]);
        float2 CtB = cmul(Ctc, Bv);
        float2 Ctp = cmul(Ctc, make_float2(pr, pi));
        float2 pB  = cmul(make_float2(pr, -pi), Bv);
        float  pp  = pr * pr + pi * pi;
        F2PACK(s_nlx[n], -lam.x, -lam.x);
        F2PACK(s_nly[n], -lam.y, -lam.y);
        F2PACK(s_cbx[n], CtB.x, CtB.x);  F2PACK(s_cby[n], CtB.y, CtB.y);
        F2PACK(s_cpx[n], Ctp.x, Ctp.x);  F2PACK(s_cpy[n], Ctp.y, Ctp.y);
        F2PACK(s_pbx[n], pB.x,  pB.x);   F2PACK(s_pby[n], pB.y,  pB.y);
        F2PACK(s_pp [n], pp,    pp);
    }
    __syncthreads();

    float tos = 2.0f * __expf(-log_step[d]);

    int j0 = jlo + 2 * tid;

    float gx[2], gy[2], ccx[2], ccy[2];
    #pragma unroll
    for (int e = 0; e < 2; e++) {
        int j = j0 + e;
        float ang = 6.283185307179586f * (float)j * (1.0f / (float)LSEQ);
        float sj, cj;
        sincosf(ang, &sj, &cj);
        float2 onep = make_float2(1.0f + cj, sj);
        float2 onem = make_float2(1.0f - cj, -sj);
        float mag = fmaxf(onep.x * onep.x + onep.y * onep.y, 1e-30f);
        float rp = 1.0f / mag;
        float2 ip = make_float2(onep.x * rp, -onep.y * rp);
        ccx[e] = 2.0f * ip.x; ccy[e] = 2.0f * ip.y;
        float2 gq = cmul(onem, ip);
        gx[e] = tos * gq.x; gy[e] = tos * gq.y;
    }
    ull gx2, gy2;
    F2PACK(gx2, gx[0], gx[1]);
    F2PACK(gy2, gy[0], gy[1]);

    ull k00x = 0, k00y = 0, k00s = 0;
    ull k01x = 0, k01y = 0, k01s = 0;
    ull k10x = 0, k10y = 0, k10s = 0;
    ull k11x = 0, k11s = 0;

    #pragma unroll 8
    for (int n = 0; n < N_STATE; n++) {
        ull dcx, dcy, m2, r, ix, t, tmp;
        F2ADD(dcx, gx2, s_nlx[n]);
        F2ADD(dcy, gy2, s_nly[n]);
        F2MUL(tmp, dcx, dcx);
        F2FMA(m2, dcy, dcy, tmp);
        float mlo, mhi, rlo, rhi;
        F2UNPK(mlo, mhi, m2);
        FRCP(rlo, mlo);
        FRCP(rhi, mhi);
        F2PACK(r, rlo, rhi);
        F2MUL(ix, dcx, r);
        F2MUL(t,  dcy, r);
        F2FMA(k00x, s_cbx[n], ix, k00x);
        F2FMA(k00x, s_cby[n], t,  k00x);
        F2FMA(k00y, s_cby[n], ix, k00y);
        F2FMA(k00s, s_cbx[n], t,  k00s);
        F2FMA(k01x, s_cpx[n], ix, k01x);
        F2FMA(k01x, s_cpy[n], t,  k01x);
        F2FMA(k01y, s_cpy[n], ix, k01y);
        F2FMA(k01s, s_cpx[n], t,  k01s);
        F2FMA(k10x, s_pbx[n], ix, k10x);
        F2FMA(k10x, s_pby[n], t,  k10x);
        F2FMA(k10y, s_pby[n], ix, k10y);
        F2FMA(k10s, s_pbx[n], t,  k10s);
        F2FMA(k11x, s_pp[n], ix, k11x);
        F2FMA(k11s, s_pp[n], t,  k11s);
    }

    float a00x[2], a00y[2], a01x[2], a01y[2], a10x[2], a10y[2], a11x[2], a11y[2];
    F2UNPK(a00x[0], a00x[1], k00x);
    { float y0,y1,s0,s1; F2UNPK(y0,y1,k00y); F2UNPK(s0,s1,k00s); a00y[0]=y0-s0; a00y[1]=y1-s1; }
    F2UNPK(a01x[0], a01x[1], k01x);
    { float y0,y1,s0,s1; F2UNPK(y0,y1,k01y); F2UNPK(s0,s1,k01s); a01y[0]=y0-s0; a01y[1]=y1-s1; }
    F2UNPK(a10x[0], a10x[1], k10x);
    { float y0,y1,s0,s1; F2UNPK(y0,y1,k10y); F2UNPK(s0,s1,k10s); a10y[0]=y0-s0; a10y[1]=y1-s1; }
    F2UNPK(a11x[0], a11x[1], k11x);
    { float s0,s1; F2UNPK(s0,s1,k11s); a11y[0]=-s0; a11y[1]=-s1; }

    float4 outv;
    #pragma unroll
    for (int e = 0; e < 2; e++) {
        float2 k00 = make_float2(a00x[e], a00y[e]);
        float2 k01 = make_float2(a01x[e], a01y[e]);
        float2 k10 = make_float2(a10x[e], a10y[e]);
        float2 den = make_float2(1.0f + a11x[e], a11y[e]);
        float rd = __fdividef(1.0f, den.x * den.x + den.y * den.y);
        float2 iden = make_float2(den.x * rd, -den.y * rd);
        float2 frac = cmul(cmul(k01, k10), iden);
        float2 res  = cmul(make_float2(ccx[e], ccy[e]), csub(k00, frac));
        if (e == 0) { outv.x = res.x; outv.y = res.y; }
        else        { outv.z = res.x; outv.w = res.y; }
    }
    *(float4*)&g_at[d * LSEQ + j0] = outv;
}

// ---------------------------------------------------------------------------
// Stage B: per channel d:
//   K = Re(DFT_2048(at_roots))/2048 ; then fold the skip connection into the
//   kernel: K'[0] += Dp[d]  (y = conv(u,K) + Dp*u == conv(u, K + Dp*delta0)).
//   Kf = DFT_4096(pad(K')) stored natural order.
// 2048 = 8*16*16; 4096 = 16^3.
// ---------------------------------------------------------------------------
__global__ void kf_kernel(const float* __restrict__ Dp)
{
    extern __shared__ float2 sm[];
    float2* tw   = sm;                 // 512 (W_4096^k, k<512)
    float2* bufA = sm + 512;           // padded 2048 -> 2184
    float2* bufB = sm + 512 + 2184;    // padded 4096 -> 4368

    int d = blockIdx.x;
    int tid = threadIdx.x;
    const int T = 256;

    for (int k = tid; k < 512; k += T) {
        float s, c;
        sincosf(6.283185307179586f * (float)k * (1.0f / 4096.0f), &s, &c);
        tw[k] = make_float2(c, -s);
    }
    for (int j = tid; j < LSEQ; j += T) bufA[PIDX(j)] = g_at[d * LSEQ + j];
    __syncthreads();

    // ---- FFT-2048 forward: radices 8,16,16 ----
    stage8 <false>(bufA, tw, 2048, 256, tid, T); __syncthreads();
    stage16<false>(bufA, tw,  256, 128, tid, T); __syncthreads();
    stage16<false>(bufA, tw,   16, 128, tid, T); __syncthreads();

    // ---- pad K' (un-digit-reverse + Dp at tap 0) into bufB ----
    float dp = Dp[d];
    for (int l = tid; l < LSEQ; l += T) {
        int p = ((l & 7) << 8) | (((l >> 3) & 15) << 4) | ((l >> 7) & 15);
        float kr = bufA[PIDX(p)].x * (1.0f / (float)LSEQ);
        if (l == 0) kr += dp;
        bufB[PIDX(l)] = make_float2(kr, 0.0f);
        bufB[PIDX(l + LSEQ)] = make_float2(0.0f, 0.0f);
    }
    __syncthreads();

    // ---- FFT-4096 forward: 16^3 ----
    stage16<false>(bufB, tw, 4096, 256, tid, T); __syncthreads();
    stage16<false>(bufB, tw,  256, 256, tid, T); __syncthreads();
    stage16<false>(bufB, tw,   16, 256, tid, T); __syncthreads();

    // natural-order coalesced global write
    for (int k = tid; k < L2X; k += T)
        g_kf[d * L2X + k] = bufB[PIDX(rev16(k))];
}

// ---------------------------------------------------------------------------
// Stage C: causal FFT conv. 4 consecutive channels per block, 2 FFT groups
// of 128 threads. Gmem via block-wide float4 only. The Dp*u skip is folded
// into Kf, so the epilogue does NOT re-read u (one 16B st per l, no ld).
// ---------------------------------------------------------------------------
__global__ __launch_bounds__(256, 3)
void conv_kernel(const float* __restrict__ u,
                 float* __restrict__ y)
{
    extern __shared__ float2 sm[];
    float2* tw   = sm;                        // 256 (W_4096^k, k<256)
    float2* buf0 = sm + 256;                  // group 0 buffer (padded 4096)
    float2* buf1 = sm + 256 + 4368;           // group 1 buffer

    int tid = threadIdx.x;
    int q   = tid >> 7;                       // group 0..1
    int gt  = tid & 127;
    float2* buf = q ? buf1 : buf0;

    int b  = blockIdx.x >> 6;                 // 16 batches
    int cb = (blockIdx.x & 63) * 4;           // block's 4-channel base
    int c0 = cb + 2 * q;                      // this group's channel pair
    int barId = 1 + q;

    if (tid < 256) {
        float s, c;
        sincosf(6.283185307179586f * (float)tid * (1.0f / 4096.0f), &s, &c);
        tw[tid] = make_float2(c, -s);
    }

    const float4* ub4 = (const float4*)(u + (size_t)b * LSEQ * D_MODEL + cb);
    float4*       yb4 = (float4*)(y + (size_t)b * LSEQ * D_MODEL + cb);

    // ---- block-wide load: one 16B ld covers both groups ----
    for (int l = tid; l < LSEQ; l += 256) {
        float4 f = ub4[(size_t)l * (D_MODEL / 4)];
        buf0[PIDX(l)] = make_float2(f.x, f.y);
        buf1[PIDX(l)] = make_float2(f.z, f.w);
    }
    for (int l = LSEQ + tid; l < L2X; l += 256) {
        buf0[PIDX(l)] = make_float2(0.0f, 0.0f);
        buf1[PIDX(l)] = make_float2(0.0f, 0.0f);
    }
    __syncthreads();

    // forward DIF: 16^3 (per group)
    stage16<false>(buf, tw, 4096, 256, gt, 128); barsync(barId, 128);
    stage16<false>(buf, tw,  256, 256, gt, 128); barsync(barId, 128);
    stage16<false>(buf, tw,   16, 256, gt, 128); barsync(barId, 128);

    // unpack packed real spectra, multiply by Kf, repack (digit-reversed smem)
    for (int k = gt; k <= 2048; k += 128) {
        int mk = (L2X - k) & (L2X - 1);
        int pk = PIDX(rev16(k));
        int pm = PIDX(rev16(mk));
        float2 Zk = buf[pk], Zm = buf[pm];
        float2 U0 = make_float2(0.5f * (Zk.x + Zm.x), 0.5f * (Zk.y - Zm.y));
        float2 U1 = make_float2(0.5f * (Zk.y + Zm.y), 0.5f * (Zm.x - Zk.x));
        float2 H0 = g_kf[(size_t)c0 * L2X + k];
        float2 H1 = g_kf[(size_t)(c0 + 1) * L2X + k];
        float2 Y0 = cmul(U0, H0);
        float2 Y1 = cmul(U1, H1);
        buf[pk] = make_float2(Y0.x - Y1.y, Y0.y + Y1.x);          // Y0 + i*Y1
        if (k != 0 && k != 2048)
            buf[pm] = make_float2(Y0.x + Y1.y, Y1.x - Y0.y);      // conj(Y0)+i*conj(Y1)
    }
    barsync(barId, 128);

    // inverse DIT (consumes digit-reversed, emits natural)
    stage16<true>(buf, tw,   16, 256, gt, 128); barsync(barId, 128);
    stage16<true>(buf, tw,  256, 256, gt, 128); barsync(barId, 128);
    stage16<true>(buf, tw, 4096, 256, gt, 128);
    __syncthreads();   // join both groups before block-wide epilogue

    // ---- block-wide epilogue: one 16B st per l (no u reload) ----
    const float invN = 1.0f / (float)L2X;
    for (int l = tid; l < LSEQ; l += 256) {
        float2 r0 = buf0[PIDX(l)];
        float2 r1 = buf1[PIDX(l)];
        float4 o;
        o.x = r0.x * invN;
        o.y = r0.y * invN;
        o.z = r1.x * invN;
        o.w = r1.y * invN;
        yb4[(size_t)l * (D_MODEL / 4)] = o;
    }
}

// ---------------------------------------------------------------------------
extern "C" void kernel_launch(void* const* d_in, const int* in_sizes, int n_in,
                              void* d_out, int out_size)
{
    const float* u         = (const float*)d_in[0];
    const float* p_ri      = (const float*)d_in[1];
    const float* lambda_ri = (const float*)d_in[2];
    const float* B_ri      = (const float*)d_in[3];
    const float* Ct_ri     = (const float*)d_in[4];
    const float* Dp        = (const float*)d_in[5];
    const float* log_step  = (const float*)d_in[6];
    float* y = (float*)d_out;

    (void)in_sizes; (void)n_in; (void)out_size;

    const int KF_SMEM   = (512 + 2184 + 4368) * sizeof(float2);   // 56512
    const int CONV_SMEM = (256 + 2 * 4368) * sizeof(float2);      // 71936

    cudaFuncSetAttribute(kf_kernel,   cudaFuncAttributeMaxDynamicSharedMemorySize, KF_SMEM);
    cudaFuncSetAttribute(conv_kernel, cudaFuncAttributeMaxDynamicSharedMemorySize, CONV_SMEM);

    at_roots_kernel<<<dim3(D_MODEL, 4), 256>>>(p_ri, lambda_ri, B_ri, Ct_ri, log_step);
    kf_kernel<<<D_MODEL, 256, KF_SMEM>>>(Dp);
    conv_kernel<<<NBATCH * 64, 256, CONV_SMEM>>>(u, y);
}